// round 5
// baseline (speedup 1.0000x reference)
#include <cuda_runtime.h>
#include <math.h>
#include <stdint.h>

#define EPSV 1e-5f

// ---------------- scratch (allocation-free: device globals) ----------------
__device__ float g_ss  [64*1024];
__device__ float g_h2  [64*512*512];
__device__ float g_xln [64*512*512];
__device__ float g_q   [64*512*512];
__device__ float g_cn  [64*768*77];
__device__ float g_k   [64*512*77];
__device__ float g_v   [64*512*77];
__device__ float g_attn[64*8*64*64];

// fast mish: x * tanh(softplus(x)) ; tanh(log u) = (u^2-1)/(u^2+1), u = 1+e^x
__device__ __forceinline__ float mishf(float x){
    float xc = fminf(x, 15.f);
    float e  = __expf(xc);
    float u  = 1.f + e;
    float u2 = u * u;
    return x * __fdividef(u2 - 1.f, u2 + 1.f);
}

// ---------------- tf32 mma helpers ------------------------------------------
__device__ __forceinline__ uint32_t f2tf32(float f){
    uint32_t r; asm("cvt.rna.tf32.f32 %0, %1;" : "=r"(r) : "f"(f)); return r;
}
__device__ __forceinline__ void mma_tf32(float* c, uint32_t a0, uint32_t a1,
                                         uint32_t a2, uint32_t a3,
                                         uint32_t b0, uint32_t b1){
    asm("mma.sync.aligned.m16n8k8.row.col.f32.tf32.tf32.f32 "
        "{%0,%1,%2,%3}, {%4,%5,%6,%7}, {%8,%9}, {%0,%1,%2,%3};"
        : "+f"(c[0]), "+f"(c[1]), "+f"(c[2]), "+f"(c[3])
        : "r"(a0), "r"(a1), "r"(a2), "r"(a3), "r"(b0), "r"(b1));
}

// ---------------- ss = mish(t) @ tm_w^T + tm_b -----------------------------
__global__ void k_ss(const float* __restrict__ t, const float* __restrict__ w,
                     const float* __restrict__ bias){
    __shared__ float tm[512];
    int b = blockIdx.x, tid = threadIdx.x;
    for (int i = tid; i < 512; i += 256) tm[i] = mishf(t[b*512 + i]);
    __syncthreads();
    for (int o = tid; o < 1024; o += 256){
        const float* wr = w + (size_t)o * 512;
        float acc = bias[o];
        #pragma unroll 8
        for (int i = 0; i < 512; i++) acc = fmaf(tm[i], wr[i], acc);
        g_ss[b*1024 + o] = acc;
    }
}

// ---------------- conv1d as implicit GEMM on tf32 tensor cores --------------
// K-major operand layout; k-permuted MMA pairs so every fragment load is LDS.128.
// MODE 0: plain bias (res conv, k/v proj)
// MODE 1: + GN + FiLM + mish      (conv0)
// MODE 2: + GN + mish + res add   (conv1)
// MODE 3: + softmax over 64 rows  (q proj)
// Block: 256 thr = 8 warps (2m x 4n). Block tile M=64(co) x N=128(l).
template<int CIN, int TAPS, int PAD, int MODE>
__global__ void k_conv(const float* __restrict__ in, const float* __restrict__ w,
                       const float* __restrict__ bias, float* __restrict__ out, int L,
                       const float* __restrict__ gg, const float* __restrict__ gb){
    constexpr int KC  = 16*TAPS;          // K per ci-chunk (16 or 80)
    constexpr int KST = KC;               // row stride (16,80: both == 16 mod 32)
    constexpr int EST = 132;              // epilogue tile row stride
    extern __shared__ __align__(16) uint32_t sm[];
    uint32_t* xsT = sm;                   // [128][KST]  n-major, k contiguous
    uint32_t* ws2 = sm + 128*KST;         // [64][KST]   m-major, k contiguous
    __shared__ float red0[256], red1[256];
    __shared__ float stA[128], stB[128];
    __shared__ float rg[64], rb[64], rsc[64], rsh[64];

    const int l0 = blockIdx.x*128, co0 = blockIdx.y*64, b = blockIdx.z;
    const int COUT = gridDim.y*64;
    const int tid = threadIdx.x, lane = tid & 31, wid = tid >> 5;
    const int wm = (wid & 1)*32, wn = (wid >> 1)*32;
    const int qr = lane >> 2, qc = lane & 3;

    float acc[2][4][4];
    #pragma unroll
    for (int mi = 0; mi < 2; mi++)
        #pragma unroll
        for (int ni = 0; ni < 4; ni++)
            #pragma unroll
            for (int r = 0; r < 4; r++) acc[mi][ni][r] = 0.f;

    const float* inb = in + (size_t)b*CIN*L;

    for (int ci0 = 0; ci0 < CIN; ci0 += 16){
        // weights: k = ci_local*TAPS + tap is contiguous in gmem
        for (int idx = tid; idx < 64*KC; idx += 256){
            int c = idx / KC, k = idx - c*KC;
            ws2[c*KST + k] = f2tf32(w[((size_t)(co0 + c)*CIN + ci0)*TAPS + k]);
        }
        // im2col, k-major, float4 stores
        for (int idx = tid; idx < 128*(KC/4); idx += 256){
            int n = idx & 127, j = idx >> 7;
            uint4 v;
            #pragma unroll
            for (int s = 0; s < 4; s++){
                int k = 4*j + s;
                int ci = k / TAPS, tap = k - ci*TAPS;
                int l = l0 + n + tap - PAD;
                float f = (l >= 0 && l < L) ? inb[(size_t)(ci0 + ci)*L + l] : 0.f;
                ((uint32_t*)&v)[s] = f2tf32(f);
            }
            *(uint4*)&xsT[n*KST + 4*j] = v;
        }
        __syncthreads();
        #pragma unroll
        for (int k16 = 0; k16 < KC/16; k16++){
            const int col = k16*16 + 4*qc;
            uint4 alo[2], ahi[2], bx[4];
            #pragma unroll
            for (int mi = 0; mi < 2; mi++){
                int m = wm + mi*16 + qr;
                alo[mi] = *(const uint4*)&ws2[ m     *KST + col];
                ahi[mi] = *(const uint4*)&ws2[(m + 8)*KST + col];
            }
            #pragma unroll
            for (int ni = 0; ni < 4; ni++)
                bx[ni] = *(const uint4*)&xsT[(wn + ni*8 + qr)*KST + col];
            #pragma unroll
            for (int mi = 0; mi < 2; mi++)
                #pragma unroll
                for (int ni = 0; ni < 4; ni++){
                    mma_tf32(acc[mi][ni], alo[mi].x, ahi[mi].x, alo[mi].y, ahi[mi].y,
                             bx[ni].x, bx[ni].y);
                    mma_tf32(acc[mi][ni], alo[mi].z, ahi[mi].z, alo[mi].w, ahi[mi].w,
                             bx[ni].z, bx[ni].w);
                }
        }
        __syncthreads();
    }

    if (MODE == 0){
        #pragma unroll
        for (int mi = 0; mi < 2; mi++){
            int r0 = co0 + wm + mi*16 + qr;
            float b0 = bias[r0], b1 = bias[r0 + 8];
            #pragma unroll
            for (int ni = 0; ni < 4; ni++){
                int c0 = l0 + wn + ni*8 + 2*qc;
                float* C = acc[mi][ni];
                if (((L & 1) == 0) && (c0 + 1) < L){
                    *(float2*)&out[((size_t)b*COUT + r0    )*L + c0] = make_float2(C[0]+b0, C[1]+b0);
                    *(float2*)&out[((size_t)b*COUT + r0 + 8)*L + c0] = make_float2(C[2]+b1, C[3]+b1);
                } else {
                    if (c0 < L){
                        out[((size_t)b*COUT + r0    )*L + c0] = C[0] + b0;
                        out[((size_t)b*COUT + r0 + 8)*L + c0] = C[2] + b1;
                    }
                    if (c0 + 1 < L){
                        out[((size_t)b*COUT + r0    )*L + c0 + 1] = C[1] + b0;
                        out[((size_t)b*COUT + r0 + 8)*L + c0 + 1] = C[3] + b1;
                    }
                }
            }
        }
        return;
    }

    // ---- fused epilogue (full 64x128 tile; L == 512 here) ----
    float* et = (float*)sm;
    #pragma unroll
    for (int mi = 0; mi < 2; mi++){
        int r0 = wm + mi*16 + qr;
        float b0 = bias[co0 + r0], b1 = bias[co0 + r0 + 8];
        #pragma unroll
        for (int ni = 0; ni < 4; ni++){
            int c0 = wn + ni*8 + 2*qc;
            float* C = acc[mi][ni];
            *(float2*)&et[ r0     *EST + c0] = make_float2(C[0]+b0, C[1]+b0);
            *(float2*)&et[(r0 + 8)*EST + c0] = make_float2(C[2]+b1, C[3]+b1);
        }
    }
    if (MODE == 1 && tid < 64){
        rg[tid]  = gg[co0 + tid];            rb[tid]  = gb[co0 + tid];
        rsc[tid] = g_ss[b*1024 + co0 + tid]; rsh[tid] = g_ss[b*1024 + 512 + co0 + tid];
    }
    if (MODE == 2 && tid < 64){
        rg[tid] = gg[co0 + tid]; rb[tid] = gb[co0 + tid];
    }
    __syncthreads();

    const int c = tid & 127, half = tid >> 7;
    if (MODE == 1 || MODE == 2){
        float s = 0.f, q = 0.f;
        #pragma unroll
        for (int r = 0; r < 32; r++){
            float v = et[(half*32 + r)*EST + c];
            s += v; q += v*v;
        }
        red0[tid] = s; red1[tid] = q;
        __syncthreads();
        if (tid < 128){
            float S = red0[tid] + red0[tid + 128];
            float Q = red1[tid] + red1[tid + 128];
            float m = S * (1.f/64.f);
            stA[tid] = m;
            stB[tid] = rsqrtf(Q * (1.f/64.f) - m*m + EPSV);
        }
        __syncthreads();
    } else { // MODE == 3: softmax over 64 rows per column
        float m = -1e30f;
        #pragma unroll
        for (int r = 0; r < 32; r++) m = fmaxf(m, et[(half*32 + r)*EST + c]);
        red0[tid] = m;
        __syncthreads();
        if (tid < 128) stA[tid] = fmaxf(red0[tid], red0[tid + 128]);
        __syncthreads();
        float s = 0.f;
        #pragma unroll
        for (int r = 0; r < 32; r++) s += __expf(et[(half*32 + r)*EST + c] - stA[c]);
        red1[tid] = s;
        __syncthreads();
        if (tid < 128) stB[tid] = 1.f / (red1[tid] + red1[tid + 128]);
        __syncthreads();
    }

    #pragma unroll 4
    for (int k = 0; k < 32; k++){
        int idx = k*256 + tid;
        int r = idx >> 7, cc = idx & 127;
        float v = et[r*EST + cc];
        size_t gidx = ((size_t)b*COUT + co0 + r)*L + l0 + cc;
        if (MODE == 1){
            v = (v - stA[cc]) * stB[cc] * rg[r] + rb[r];
            v = v * (1.f + rsc[r]) + rsh[r];
            v = mishf(v);
        } else if (MODE == 2){
            v = (v - stA[cc]) * stB[cc] * rg[r] + rb[r];
            v = mishf(v) + out[gidx];
        } else { // MODE == 3
            v = __expf(v - stA[cc]) * stB[cc];
        }
        out[gidx] = v;
    }
}

// ---------------- LN over channels of out[cidx[b]] -> g_xln (b,c,t) ---------
__global__ void k_xln(const float* __restrict__ out, const float* __restrict__ gg,
                      const float* __restrict__ gb, const int* __restrict__ cidx){
    int b = blockIdx.y;
    int t = blockIdx.x*128 + threadIdx.x;
    int bi = cidx[b];
    const float* src = out + (size_t)bi*512*512 + t;
    float s = 0.f, q = 0.f;
    for (int c = 0; c < 512; c++){ float v = src[(size_t)c*512]; s += v; q += v*v; }
    float m = s * (1.f/512.f);
    float r = rsqrtf(q * (1.f/512.f) - m*m + EPSV);
    float* dst = g_xln + (size_t)b*512*512 + t;
    for (int c = 0; c < 512; c++){
        float v = src[(size_t)c*512];
        dst[(size_t)c*512] = (v - m) * r * gg[c] + gb[c];
    }
}

// ---------------- LN(cond[cidx[b]]) -> g_cn (b, 768, 77) transposed ---------
__global__ void k_cn(const float* __restrict__ cond, const float* __restrict__ gg,
                     const float* __restrict__ gb, const int* __restrict__ cidx){
    __shared__ float row[768];
    __shared__ float wsum[8], wsq[8];
    int n = blockIdx.x, b = blockIdx.y;
    int bi = cidx[b];
    int tid = threadIdx.x, lane = tid & 31, w = tid >> 5;
    const float* src = cond + ((size_t)bi*77 + n)*768;
    float s = 0.f, q = 0.f;
    for (int i = tid; i < 768; i += 256){ float v = src[i]; row[i] = v; s += v; q += v*v; }
    #pragma unroll
    for (int o = 16; o; o >>= 1){ s += __shfl_xor_sync(0xffffffffu, s, o); q += __shfl_xor_sync(0xffffffffu, q, o); }
    if (lane == 0){ wsum[w] = s; wsq[w] = q; }
    __syncthreads();
    if (tid == 0){
        float S = 0.f, Q = 0.f;
        #pragma unroll
        for (int i = 0; i < 8; i++){ S += wsum[i]; Q += wsq[i]; }
        float m = S * (1.f/768.f); float var = Q * (1.f/768.f) - m*m;
        wsum[0] = m; wsq[0] = rsqrtf(var + EPSV);
    }
    __syncthreads();
    float m = wsum[0], r = wsq[0];
    for (int i = tid; i < 768; i += 256)
        g_cn[((size_t)b*768 + i)*77 + n] = (row[i] - m) * r * gg[i] + gb[i];
}

// ---------------- k softmax over n (77) at fixed (b,d) ----------------------
__global__ void k_ksm(float* __restrict__ kbuf){
    int b = blockIdx.x;
    int d = blockIdx.y*8 + (threadIdx.x >> 5);
    int lane = threadIdx.x & 31;
    float* row = kbuf + ((size_t)b*512 + d)*77;
    float v0 = row[lane];
    float v1 = row[lane + 32];
    bool has2 = (lane + 64) < 77;
    float v2 = has2 ? row[lane + 64] : -1e30f;
    float m = fmaxf(fmaxf(v0, v1), v2);
    #pragma unroll
    for (int o = 16; o; o >>= 1) m = fmaxf(m, __shfl_xor_sync(0xffffffffu, m, o));
    float e0 = __expf(v0 - m), e1 = __expf(v1 - m), e2 = has2 ? __expf(v2 - m) : 0.f;
    float s = e0 + e1 + e2;
    #pragma unroll
    for (int o = 16; o; o >>= 1) s += __shfl_xor_sync(0xffffffffu, s, o);
    float inv = 1.f / s;
    row[lane] = e0 * inv;
    row[lane + 32] = e1 * inv;
    if (has2) row[lane + 64] = e2 * inv;
}

// ---------------- attn[b,h,d,l] = sum_n k[b,hd+d,n] * v[b,hd+l,n] ------------
__global__ void k_attn(const float* __restrict__ kbuf, const float* __restrict__ vbuf){
    __shared__ float ks[64][80], vs[64][80];
    int h = blockIdx.x, b = blockIdx.y;
    int tid = threadIdx.x, tx = tid & 15, ty = tid >> 4;
    const float* kp = kbuf + ((size_t)(b*512 + h*64))*77;
    const float* vp = vbuf + ((size_t)(b*512 + h*64))*77;
    for (int idx = tid; idx < 64*80; idx += 256){
        int r = idx / 80, c = idx - r*80;
        float kv = (c < 77) ? kp[(size_t)r*77 + c] : 0.f;
        float vv = (c < 77) ? vp[(size_t)r*77 + c] : 0.f;
        ks[r][c] = kv; vs[r][c] = vv;
    }
    __syncthreads();
    float acc[4][4];
    #pragma unroll
    for (int i = 0; i < 4; i++)
        #pragma unroll
        for (int j = 0; j < 4; j++) acc[i][j] = 0.f;
    for (int n = 0; n < 77; n++){
        float a[4], c4[4];
        #pragma unroll
        for (int i = 0; i < 4; i++) a[i] = ks[ty*4 + i][n];
        #pragma unroll
        for (int j = 0; j < 4; j++) c4[j] = vs[tx*4 + j][n];
        #pragma unroll
        for (int i = 0; i < 4; i++)
            #pragma unroll
            for (int j = 0; j < 4; j++) acc[i][j] = fmaf(a[i], c4[j], acc[i][j]);
    }
    #pragma unroll
    for (int i = 0; i < 4; i++)
        #pragma unroll
        for (int j = 0; j < 4; j++)
            g_attn[(((size_t)(b*8 + h))*64 + ty*4 + i)*64 + tx*4 + j] = acc[i][j];
}

// ---------------- y = q @ attn, add into d_out (cidx unique by construction) -
__global__ void k_y(const float* __restrict__ q, float* __restrict__ out,
                    const int* __restrict__ cidx){
    __shared__ __align__(16) float qs[64][128];
    __shared__ float as[64][64];
    int t0 = blockIdx.x*128, h = blockIdx.y, b = blockIdx.z;
    int bi = cidx[b];
    int tid = threadIdx.x, tx = tid & 15, ty = tid >> 4;
    for (int idx = tid; idx < 64*128; idx += 256){
        int r = idx >> 7, c = idx & 127;
        qs[r][c] = q[((size_t)(b*512 + h*64 + r))*512 + t0 + c];
    }
    for (int idx = tid; idx < 64*64; idx += 256){
        int r = idx >> 6, c = idx & 63;
        as[r][c] = g_attn[(((size_t)(b*8 + h))*64 + r)*64 + c];
    }
    __syncthreads();
    float acc[4][8];
    #pragma unroll
    for (int i = 0; i < 4; i++)
        #pragma unroll
        for (int j = 0; j < 8; j++) acc[i][j] = 0.f;
    for (int d = 0; d < 64; d++){
        float4 q0 = *reinterpret_cast<const float4*>(&qs[d][tx*8]);
        float4 q1 = *reinterpret_cast<const float4*>(&qs[d][tx*8 + 4]);
        float qr[8] = {q0.x,q0.y,q0.z,q0.w,q1.x,q1.y,q1.z,q1.w};
        float ar[4];
        #pragma unroll
        for (int i = 0; i < 4; i++) ar[i] = as[d][ty*4 + i];
        #pragma unroll
        for (int i = 0; i < 4; i++)
            #pragma unroll
            for (int j = 0; j < 8; j++) acc[i][j] = fmaf(ar[i], qr[j], acc[i][j]);
    }
    #pragma unroll
    for (int i = 0; i < 4; i++){
        int ch = h*64 + ty*4 + i;
        float* dst = &out[((size_t)bi*512 + ch)*512 + t0 + tx*8];
        float4 o0 = *(float4*)dst;
        float4 o1 = *(float4*)(dst + 4);
        o0.x += acc[i][0]; o0.y += acc[i][1]; o0.z += acc[i][2]; o0.w += acc[i][3];
        o1.x += acc[i][4]; o1.y += acc[i][5]; o1.z += acc[i][6]; o1.w += acc[i][7];
        *(float4*)dst = o0;
        *(float4*)(dst + 4) = o1;
    }
}

// ---------------- launch ----------------------------------------------------
extern "C" void kernel_launch(void* const* d_in, const int* in_sizes, int n_in,
                              void* d_out, int out_size){
    const float* x       = (const float*)d_in[0];
    const float* t       = (const float*)d_in[1];
    const float* cond    = (const float*)d_in[2];
    const float* conv0_w = (const float*)d_in[3];
    const float* conv0_b = (const float*)d_in[4];
    const float* gn0_g   = (const float*)d_in[5];
    const float* gn0_b   = (const float*)d_in[6];
    const float* tm_w    = (const float*)d_in[7];
    const float* tm_b    = (const float*)d_in[8];
    const float* conv1_w = (const float*)d_in[9];
    const float* conv1_b = (const float*)d_in[10];
    const float* gn1_g   = (const float*)d_in[11];
    const float* gn1_b   = (const float*)d_in[12];
    const float* res_w   = (const float*)d_in[13];
    const float* res_b   = (const float*)d_in[14];
    const float* ln_x_g  = (const float*)d_in[15];
    const float* ln_x_b  = (const float*)d_in[16];
    const float* ln_c_g  = (const float*)d_in[17];
    const float* ln_c_b  = (const float*)d_in[18];
    const float* q_w     = (const float*)d_in[19];
    const float* q_b     = (const float*)d_in[20];
    const float* k_w     = (const float*)d_in[21];
    const float* k_b     = (const float*)d_in[22];
    const float* v_w     = (const float*)d_in[23];
    const float* v_b     = (const float*)d_in[24];
    const int*   cidx    = (const int*)d_in[25];
    float* out = (float*)d_out;

    float *p_h2, *p_xln, *p_q, *p_cn, *p_k, *p_v;
    cudaGetSymbolAddress((void**)&p_h2,  g_h2);
    cudaGetSymbolAddress((void**)&p_xln, g_xln);
    cudaGetSymbolAddress((void**)&p_q,   g_q);
    cudaGetSymbolAddress((void**)&p_cn,  g_cn);
    cudaGetSymbolAddress((void**)&p_k,   g_k);
    cudaGetSymbolAddress((void**)&p_v,   g_v);

    // dynamic smem sizes (u32 counts: 192*KST; plus epilogue floor 8448)
    const int smem5 = 192*80*4;          // 61440 B for 5-tap convs
    const int smem1 = 192*16*4;          // 12288 B for 1-tap MODE0
    const int smem3 = 8448*4;            // 33792 B for MODE3 (epilogue tile)
    cudaFuncSetAttribute(k_conv<256,5,2,1>, cudaFuncAttributeMaxDynamicSharedMemorySize, smem5);
    cudaFuncSetAttribute(k_conv<512,5,2,2>, cudaFuncAttributeMaxDynamicSharedMemorySize, smem5);
    cudaFuncSetAttribute(k_conv<512,1,0,3>, cudaFuncAttributeMaxDynamicSharedMemorySize, smem3);

    // FiLM scale/shift
    k_ss<<<64, 256>>>(t, tm_w, tm_b);
    // residual 1x1 conv -> d_out (must precede fused conv1)
    k_conv<256,1,0,0><<<dim3(4,8,64), 256, smem1>>>(x, res_w, res_b, out, 512, nullptr, nullptr);
    // conv0 + GN0 + FiLM + mish -> g_h2
    k_conv<256,5,2,1><<<dim3(4,8,64), 256, smem5>>>(x, conv0_w, conv0_b, p_h2, 512, gn0_g, gn0_b);
    // conv1 + GN1 + mish + residual add -> d_out
    k_conv<512,5,2,2><<<dim3(4,8,64), 256, smem5>>>(p_h2, conv1_w, conv1_b, out, 512, gn1_g, gn1_b);
    // LN over channels of out[cidx] -> g_xln (b,c,t)
    k_xln<<<dim3(4,64), 128>>>(out, ln_x_g, ln_x_b, cidx);
    // q projection + softmax over head-dim -> g_q
    k_conv<512,1,0,3><<<dim3(4,8,64), 256, smem3>>>(p_xln, q_w, q_b, p_q, 512, nullptr, nullptr);
    // LN(cond[cidx]) -> g_cn (b, 768, 77)
    k_cn<<<dim3(77,64), 256>>>(cond, ln_c_g, ln_c_b, cidx);
    // k,v projections (1x1 conv over 768 ch, L=77)
    k_conv<768,1,0,0><<<dim3(1,8,64), 256, smem1>>>(p_cn, k_w, k_b, p_k, 77, nullptr, nullptr);
    k_conv<768,1,0,0><<<dim3(1,8,64), 256, smem1>>>(p_cn, v_w, v_b, p_v, 77, nullptr, nullptr);
    // k softmax over n
    k_ksm<<<dim3(64,64), 256>>>(p_k);
    // attn = k^T v per (b,h)
    k_attn<<<dim3(8,64), 256>>>(p_k, p_v);
    // y = q @ attn, add into d_out
    k_y<<<dim3(4,8,64), 256>>>(p_q, out, cidx);
}

// round 6
// speedup vs baseline: 1.7279x; 1.7279x over previous
#include <cuda_runtime.h>
#include <math.h>
#include <stdint.h>

#define EPSV 1e-5f

// ---------------- scratch (allocation-free: device globals) ----------------
__device__ float g_ss  [64*1024];
__device__ float g_h2  [64*512*512];
__device__ float g_xln [64*512*512];
__device__ float g_q   [64*512*512];
__device__ float g_cn  [64*768*77];
__device__ float g_k   [64*512*77];
__device__ float g_v   [64*512*77];
__device__ float g_attn[64*8*64*64];

// fast mish: x * tanh(softplus(x)) ; tanh(log u) = (u^2-1)/(u^2+1), u = 1+e^x
__device__ __forceinline__ float mishf(float x){
    float xc = fminf(x, 15.f);
    float e  = __expf(xc);
    float u  = 1.f + e;
    float u2 = u * u;
    return x * __fdividef(u2 - 1.f, u2 + 1.f);
}

// ---------------- tf32 mma helpers ------------------------------------------
__device__ __forceinline__ uint32_t f2tf32(float f){
    uint32_t r; asm("cvt.rna.tf32.f32 %0, %1;" : "=r"(r) : "f"(f)); return r;
}
__device__ __forceinline__ void mma_tf32(float* c, uint32_t a0, uint32_t a1,
                                         uint32_t a2, uint32_t a3,
                                         uint32_t b0, uint32_t b1){
    asm("mma.sync.aligned.m16n8k8.row.col.f32.tf32.tf32.f32 "
        "{%0,%1,%2,%3}, {%4,%5,%6,%7}, {%8,%9}, {%0,%1,%2,%3};"
        : "+f"(c[0]), "+f"(c[1]), "+f"(c[2]), "+f"(c[3])
        : "r"(a0), "r"(a1), "r"(a2), "r"(a3), "r"(b0), "r"(b1));
}

// ---------------- cp.async helpers -------------------------------------------
__device__ __forceinline__ void cp4(uint32_t dst, const void* src, bool pred){
    int sz = pred ? 4 : 0;
    asm volatile("cp.async.ca.shared.global [%0], [%1], 4, %2;"
                 :: "r"(dst), "l"(src), "r"(sz));
}
__device__ __forceinline__ void cp16(uint32_t dst, const void* src){
    asm volatile("cp.async.cg.shared.global [%0], [%1], 16;" :: "r"(dst), "l"(src));
}
__device__ __forceinline__ void cp_commit(){
    asm volatile("cp.async.commit_group;");
}
template<int N>
__device__ __forceinline__ void cp_wait(){
    asm volatile("cp.async.wait_group %0;" :: "n"(N));
}

// ---------------- ss = mish(t) @ tm_w^T + tm_b -----------------------------
__global__ void k_ss(const float* __restrict__ t, const float* __restrict__ w,
                     const float* __restrict__ bias){
    __shared__ float tm[512];
    int b = blockIdx.x, tid = threadIdx.x;
    for (int i = tid; i < 512; i += 256) tm[i] = mishf(t[b*512 + i]);
    __syncthreads();
    for (int o = tid; o < 1024; o += 256){
        const float* wr = w + (size_t)o * 512;
        float acc = bias[o];
        #pragma unroll 8
        for (int i = 0; i < 512; i++) acc = fmaf(tm[i], wr[i], acc);
        g_ss[b*1024 + o] = acc;
    }
}

// ---------------- conv1d as implicit GEMM on tf32 tensor cores --------------
// R4 data layout + cp.async 2-stage double-buffered pipeline.
// MODE 0: plain bias (res conv, k/v proj)
// MODE 1: + GN + FiLM + mish      (conv0)
// MODE 2: + GN + mish + res add   (conv1)
// MODE 3: + softmax over 64 rows  (q proj)
// Block: 256 thr = 8 warps (2m x 4n). Block tile M=64(co) x N=128(l).
template<int CIN, int TAPS, int PAD, int MODE>
__global__ void k_conv(const float* __restrict__ in, const float* __restrict__ w,
                       const float* __restrict__ bias, float* __restrict__ out, int L,
                       const float* __restrict__ gg, const float* __restrict__ gb){
    constexpr int LWD = 128 + TAPS - 1;   // valid data columns in xs
    constexpr int LWS = 136;              // padded xs row stride (floats)
    constexpr int KCH = 16*TAPS;          // weights per co per chunk
    constexpr int WST = KCH + 4;          // ws row stride (floats)
    constexpr int CHUNK = 16*LWS + 64*WST; // floats per stage
    constexpr int EST = 132;              // epilogue tile row stride
    extern __shared__ __align__(16) float smf[];
    __shared__ float red0[256], red1[256];
    __shared__ float stA[128], stB[128];
    __shared__ float rg[64], rb[64], rsc[64], rsh[64];

    const int l0 = blockIdx.x*128, co0 = blockIdx.y*64, b = blockIdx.z;
    const int COUT = gridDim.y*64;
    const int tid = threadIdx.x, lane = tid & 31, wid = tid >> 5;
    const int wm = (wid & 1)*32, wn = (wid >> 1)*32;
    const int qr = lane >> 2, qc = lane & 3;
    const uint32_t smaddr = (uint32_t)__cvta_generic_to_shared(smf);

    float acc[2][4][4];
    #pragma unroll
    for (int mi = 0; mi < 2; mi++)
        #pragma unroll
        for (int ni = 0; ni < 4; ni++)
            #pragma unroll
            for (int r = 0; r < 4; r++) acc[mi][ni][r] = 0.f;

    const float* inb = in + (size_t)b*CIN*L;

    auto fill = [&](int ci0, int stg){
        uint32_t xsA = smaddr + stg*CHUNK*4;
        uint32_t wsA = xsA + 16*LWS*4;
        for (int idx = tid; idx < 16*LWD; idx += 256){
            int r = idx / LWD, c = idx - r*LWD;
            int l = l0 + c - PAD;
            bool ok = (l >= 0 && l < L);
            int lc = ok ? l : 0;
            cp4(xsA + (r*LWS + c)*4, inb + (size_t)(ci0 + r)*L + lc, ok);
        }
        for (int idx = tid; idx < 64*(KCH/4); idx += 256){
            int c = idx / (KCH/4), j = idx - c*(KCH/4);
            cp16(wsA + (c*WST + 4*j)*4,
                 w + ((size_t)(co0 + c)*CIN + ci0)*TAPS + 4*j);
        }
    };

    const int NCH = CIN/16;
    fill(0, 0);
    cp_commit();

    for (int ch = 0; ch < NCH; ch++){
        if (ch + 1 < NCH) fill((ch + 1)*16, (ch + 1) & 1);
        cp_commit();
        cp_wait<1>();
        __syncthreads();

        const float (*xs)[LWS] = (const float(*)[LWS])(smf + (ch & 1)*CHUNK);
        const float (*ws)[WST] = (const float(*)[WST])(smf + (ch & 1)*CHUNK + 16*LWS);

        #pragma unroll
        for (int tap = 0; tap < TAPS; tap++){
            #pragma unroll
            for (int ks = 0; ks < 2; ks++){
                uint32_t A[2][4], B[4][2];
                const int k0 = ks*8 + qc;
                #pragma unroll
                for (int mi = 0; mi < 2; mi++){
                    int m = wm + mi*16 + qr;
                    A[mi][0] = f2tf32(ws[m    ][ k0     *TAPS + tap]);
                    A[mi][1] = f2tf32(ws[m + 8][ k0     *TAPS + tap]);
                    A[mi][2] = f2tf32(ws[m    ][(k0 + 4)*TAPS + tap]);
                    A[mi][3] = f2tf32(ws[m + 8][(k0 + 4)*TAPS + tap]);
                }
                #pragma unroll
                for (int ni = 0; ni < 4; ni++){
                    int n = wn + ni*8 + qr + tap;
                    B[ni][0] = f2tf32(xs[k0    ][n]);
                    B[ni][1] = f2tf32(xs[k0 + 4][n]);
                }
                #pragma unroll
                for (int mi = 0; mi < 2; mi++)
                    #pragma unroll
                    for (int ni = 0; ni < 4; ni++){
                        mma_tf32(acc[mi][ni], A[mi][0], A[mi][1], A[mi][2], A[mi][3],
                                 B[ni][0], B[ni][1]);
                    }
            }
        }
        __syncthreads();
    }

    if (MODE == 0){
        #pragma unroll
        for (int mi = 0; mi < 2; mi++){
            int r0 = co0 + wm + mi*16 + qr;
            float b0 = bias[r0], b1 = bias[r0 + 8];
            #pragma unroll
            for (int ni = 0; ni < 4; ni++){
                int c0 = l0 + wn + ni*8 + 2*qc;
                float* C = acc[mi][ni];
                if (((L & 1) == 0) && (c0 + 1) < L){
                    *(float2*)&out[((size_t)b*COUT + r0    )*L + c0] = make_float2(C[0]+b0, C[1]+b0);
                    *(float2*)&out[((size_t)b*COUT + r0 + 8)*L + c0] = make_float2(C[2]+b1, C[3]+b1);
                } else {
                    if (c0 < L){
                        out[((size_t)b*COUT + r0    )*L + c0] = C[0] + b0;
                        out[((size_t)b*COUT + r0 + 8)*L + c0] = C[2] + b1;
                    }
                    if (c0 + 1 < L){
                        out[((size_t)b*COUT + r0    )*L + c0 + 1] = C[1] + b0;
                        out[((size_t)b*COUT + r0 + 8)*L + c0 + 1] = C[3] + b1;
                    }
                }
            }
        }
        return;
    }

    // ---- fused epilogue (full 64x128 tile; L == 512 here) ----
    float* et = smf;
    #pragma unroll
    for (int mi = 0; mi < 2; mi++){
        int r0 = wm + mi*16 + qr;
        float b0 = bias[co0 + r0], b1 = bias[co0 + r0 + 8];
        #pragma unroll
        for (int ni = 0; ni < 4; ni++){
            int c0 = wn + ni*8 + 2*qc;
            float* C = acc[mi][ni];
            *(float2*)&et[ r0     *EST + c0] = make_float2(C[0]+b0, C[1]+b0);
            *(float2*)&et[(r0 + 8)*EST + c0] = make_float2(C[2]+b1, C[3]+b1);
        }
    }
    if (MODE == 1 && tid < 64){
        rg[tid]  = gg[co0 + tid];            rb[tid]  = gb[co0 + tid];
        rsc[tid] = g_ss[b*1024 + co0 + tid]; rsh[tid] = g_ss[b*1024 + 512 + co0 + tid];
    }
    if (MODE == 2 && tid < 64){
        rg[tid] = gg[co0 + tid]; rb[tid] = gb[co0 + tid];
    }
    __syncthreads();

    const int c = tid & 127, half = tid >> 7;
    if (MODE == 1 || MODE == 2){
        float s = 0.f, q = 0.f;
        #pragma unroll
        for (int r = 0; r < 32; r++){
            float v = et[(half*32 + r)*EST + c];
            s += v; q += v*v;
        }
        red0[tid] = s; red1[tid] = q;
        __syncthreads();
        if (tid < 128){
            float S = red0[tid] + red0[tid + 128];
            float Q = red1[tid] + red1[tid + 128];
            float m = S * (1.f/64.f);
            stA[tid] = m;
            stB[tid] = rsqrtf(Q * (1.f/64.f) - m*m + EPSV);
        }
        __syncthreads();
    } else { // MODE == 3: softmax over 64 rows per column
        float m = -1e30f;
        #pragma unroll
        for (int r = 0; r < 32; r++) m = fmaxf(m, et[(half*32 + r)*EST + c]);
        red0[tid] = m;
        __syncthreads();
        if (tid < 128) stA[tid] = fmaxf(red0[tid], red0[tid + 128]);
        __syncthreads();
        float s = 0.f;
        #pragma unroll
        for (int r = 0; r < 32; r++) s += __expf(et[(half*32 + r)*EST + c] - stA[c]);
        red1[tid] = s;
        __syncthreads();
        if (tid < 128) stB[tid] = 1.f / (red1[tid] + red1[tid + 128]);
        __syncthreads();
    }

    #pragma unroll 4
    for (int k = 0; k < 32; k++){
        int idx = k*256 + tid;
        int r = idx >> 7, cc = idx & 127;
        float v = et[r*EST + cc];
        size_t gidx = ((size_t)b*COUT + co0 + r)*L + l0 + cc;
        if (MODE == 1){
            v = (v - stA[cc]) * stB[cc] * rg[r] + rb[r];
            v = v * (1.f + rsc[r]) + rsh[r];
            v = mishf(v);
        } else if (MODE == 2){
            v = (v - stA[cc]) * stB[cc] * rg[r] + rb[r];
            v = mishf(v) + out[gidx];
        } else { // MODE == 3
            v = __expf(v - stA[cc]) * stB[cc];
        }
        out[gidx] = v;
    }
}

// ---------------- LN over channels of out[cidx[b]] -> g_xln (b,c,t) ---------
__global__ void k_xln(const float* __restrict__ out, const float* __restrict__ gg,
                      const float* __restrict__ gb, const int* __restrict__ cidx){
    int b = blockIdx.y;
    int t = blockIdx.x*128 + threadIdx.x;
    int bi = cidx[b];
    const float* src = out + (size_t)bi*512*512 + t;
    float s = 0.f, q = 0.f;
    for (int c = 0; c < 512; c++){ float v = src[(size_t)c*512]; s += v; q += v*v; }
    float m = s * (1.f/512.f);
    float r = rsqrtf(q * (1.f/512.f) - m*m + EPSV);
    float* dst = g_xln + (size_t)b*512*512 + t;
    for (int c = 0; c < 512; c++){
        float v = src[(size_t)c*512];
        dst[(size_t)c*512] = (v - m) * r * gg[c] + gb[c];
    }
}

// ---------------- LN(cond[cidx[b]]) -> g_cn (b, 768, 77) transposed ---------
__global__ void k_cn(const float* __restrict__ cond, const float* __restrict__ gg,
                     const float* __restrict__ gb, const int* __restrict__ cidx){
    __shared__ float row[768];
    __shared__ float wsum[8], wsq[8];
    int n = blockIdx.x, b = blockIdx.y;
    int bi = cidx[b];
    int tid = threadIdx.x, lane = tid & 31, w = tid >> 5;
    const float* src = cond + ((size_t)bi*77 + n)*768;
    float s = 0.f, q = 0.f;
    for (int i = tid; i < 768; i += 256){ float v = src[i]; row[i] = v; s += v; q += v*v; }
    #pragma unroll
    for (int o = 16; o; o >>= 1){ s += __shfl_xor_sync(0xffffffffu, s, o); q += __shfl_xor_sync(0xffffffffu, q, o); }
    if (lane == 0){ wsum[w] = s; wsq[w] = q; }
    __syncthreads();
    if (tid == 0){
        float S = 0.f, Q = 0.f;
        #pragma unroll
        for (int i = 0; i < 8; i++){ S += wsum[i]; Q += wsq[i]; }
        float m = S * (1.f/768.f); float var = Q * (1.f/768.f) - m*m;
        wsum[0] = m; wsq[0] = rsqrtf(var + EPSV);
    }
    __syncthreads();
    float m = wsum[0], r = wsq[0];
    for (int i = tid; i < 768; i += 256)
        g_cn[((size_t)b*768 + i)*77 + n] = (row[i] - m) * r * gg[i] + gb[i];
}

// ---------------- k softmax over n (77) at fixed (b,d) ----------------------
__global__ void k_ksm(float* __restrict__ kbuf){
    int b = blockIdx.x;
    int d = blockIdx.y*8 + (threadIdx.x >> 5);
    int lane = threadIdx.x & 31;
    float* row = kbuf + ((size_t)b*512 + d)*77;
    float v0 = row[lane];
    float v1 = row[lane + 32];
    bool has2 = (lane + 64) < 77;
    float v2 = has2 ? row[lane + 64] : -1e30f;
    float m = fmaxf(fmaxf(v0, v1), v2);
    #pragma unroll
    for (int o = 16; o; o >>= 1) m = fmaxf(m, __shfl_xor_sync(0xffffffffu, m, o));
    float e0 = __expf(v0 - m), e1 = __expf(v1 - m), e2 = has2 ? __expf(v2 - m) : 0.f;
    float s = e0 + e1 + e2;
    #pragma unroll
    for (int o = 16; o; o >>= 1) s += __shfl_xor_sync(0xffffffffu, s, o);
    float inv = 1.f / s;
    row[lane] = e0 * inv;
    row[lane + 32] = e1 * inv;
    if (has2) row[lane + 64] = e2 * inv;
}

// ---------------- attn[b,h,d,l] = sum_n k[b,hd+d,n] * v[b,hd+l,n] ------------
__global__ void k_attn(const float* __restrict__ kbuf, const float* __restrict__ vbuf){
    __shared__ float ks[64][80], vs[64][80];
    int h = blockIdx.x, b = blockIdx.y;
    int tid = threadIdx.x, tx = tid & 15, ty = tid >> 4;
    const float* kp = kbuf + ((size_t)(b*512 + h*64))*77;
    const float* vp = vbuf + ((size_t)(b*512 + h*64))*77;
    for (int idx = tid; idx < 64*80; idx += 256){
        int r = idx / 80, c = idx - r*80;
        float kv = (c < 77) ? kp[(size_t)r*77 + c] : 0.f;
        float vv = (c < 77) ? vp[(size_t)r*77 + c] : 0.f;
        ks[r][c] = kv; vs[r][c] = vv;
    }
    __syncthreads();
    float acc[4][4];
    #pragma unroll
    for (int i = 0; i < 4; i++)
        #pragma unroll
        for (int j = 0; j < 4; j++) acc[i][j] = 0.f;
    for (int n = 0; n < 77; n++){
        float a[4], c4[4];
        #pragma unroll
        for (int i = 0; i < 4; i++) a[i] = ks[ty*4 + i][n];
        #pragma unroll
        for (int j = 0; j < 4; j++) c4[j] = vs[tx*4 + j][n];
        #pragma unroll
        for (int i = 0; i < 4; i++)
            #pragma unroll
            for (int j = 0; j < 4; j++) acc[i][j] = fmaf(a[i], c4[j], acc[i][j]);
    }
    #pragma unroll
    for (int i = 0; i < 4; i++)
        #pragma unroll
        for (int j = 0; j < 4; j++)
            g_attn[(((size_t)(b*8 + h))*64 + ty*4 + i)*64 + tx*4 + j] = acc[i][j];
}

// ---------------- y = q @ attn, add into d_out (cidx unique by construction) -
__global__ void k_y(const float* __restrict__ q, float* __restrict__ out,
                    const int* __restrict__ cidx){
    __shared__ __align__(16) float qs[64][128];
    __shared__ float as[64][64];
    int t0 = blockIdx.x*128, h = blockIdx.y, b = blockIdx.z;
    int bi = cidx[b];
    int tid = threadIdx.x, tx = tid & 15, ty = tid >> 4;
    for (int idx = tid; idx < 64*128; idx += 256){
        int r = idx >> 7, c = idx & 127;
        qs[r][c] = q[((size_t)(b*512 + h*64 + r))*512 + t0 + c];
    }
    for (int idx = tid; idx < 64*64; idx += 256){
        int r = idx >> 6, c = idx & 63;
        as[r][c] = g_attn[(((size_t)(b*8 + h))*64 + r)*64 + c];
    }
    __syncthreads();
    float acc[4][8];
    #pragma unroll
    for (int i = 0; i < 4; i++)
        #pragma unroll
        for (int j = 0; j < 8; j++) acc[i][j] = 0.f;
    for (int d = 0; d < 64; d++){
        float4 q0 = *reinterpret_cast<const float4*>(&qs[d][tx*8]);
        float4 q1 = *reinterpret_cast<const float4*>(&qs[d][tx*8 + 4]);
        float qr[8] = {q0.x,q0.y,q0.z,q0.w,q1.x,q1.y,q1.z,q1.w};
        float ar[4];
        #pragma unroll
        for (int i = 0; i < 4; i++) ar[i] = as[d][ty*4 + i];
        #pragma unroll
        for (int i = 0; i < 4; i++)
            #pragma unroll
            for (int j = 0; j < 8; j++) acc[i][j] = fmaf(ar[i], qr[j], acc[i][j]);
    }
    #pragma unroll
    for (int i = 0; i < 4; i++){
        int ch = h*64 + ty*4 + i;
        float* dst = &out[((size_t)bi*512 + ch)*512 + t0 + tx*8];
        float4 o0 = *(float4*)dst;
        float4 o1 = *(float4*)(dst + 4);
        o0.x += acc[i][0]; o0.y += acc[i][1]; o0.z += acc[i][2]; o0.w += acc[i][3];
        o1.x += acc[i][4]; o1.y += acc[i][5]; o1.z += acc[i][6]; o1.w += acc[i][7];
        *(float4*)dst = o0;
        *(float4*)(dst + 4) = o1;
    }
}

// ---------------- launch ----------------------------------------------------
extern "C" void kernel_launch(void* const* d_in, const int* in_sizes, int n_in,
                              void* d_out, int out_size){
    const float* x       = (const float*)d_in[0];
    const float* t       = (const float*)d_in[1];
    const float* cond    = (const float*)d_in[2];
    const float* conv0_w = (const float*)d_in[3];
    const float* conv0_b = (const float*)d_in[4];
    const float* gn0_g   = (const float*)d_in[5];
    const float* gn0_b   = (const float*)d_in[6];
    const float* tm_w    = (const float*)d_in[7];
    const float* tm_b    = (const float*)d_in[8];
    const float* conv1_w = (const float*)d_in[9];
    const float* conv1_b = (const float*)d_in[10];
    const float* gn1_g   = (const float*)d_in[11];
    const float* gn1_b   = (const float*)d_in[12];
    const float* res_w   = (const float*)d_in[13];
    const float* res_b   = (const float*)d_in[14];
    const float* ln_x_g  = (const float*)d_in[15];
    const float* ln_x_b  = (const float*)d_in[16];
    const float* ln_c_g  = (const float*)d_in[17];
    const float* ln_c_b  = (const float*)d_in[18];
    const float* q_w     = (const float*)d_in[19];
    const float* q_b     = (const float*)d_in[20];
    const float* k_w     = (const float*)d_in[21];
    const float* k_b     = (const float*)d_in[22];
    const float* v_w     = (const float*)d_in[23];
    const float* v_b     = (const float*)d_in[24];
    const int*   cidx    = (const int*)d_in[25];
    float* out = (float*)d_out;

    float *p_h2, *p_xln, *p_q, *p_cn, *p_k, *p_v;
    cudaGetSymbolAddress((void**)&p_h2,  g_h2);
    cudaGetSymbolAddress((void**)&p_xln, g_xln);
    cudaGetSymbolAddress((void**)&p_q,   g_q);
    cudaGetSymbolAddress((void**)&p_cn,  g_cn);
    cudaGetSymbolAddress((void**)&p_k,   g_k);
    cudaGetSymbolAddress((void**)&p_v,   g_v);

    // dynamic smem: 2 stages of (16*136 + 64*WST) floats
    const int smem5 = 2*(16*136 + 64*84)*4;   // 60416 B (5-tap)
    const int smem1 = 2*(16*136 + 64*20)*4;   // 27648 B (1-tap MODE0)
    const int smem3 = 8448*4;                 // 33792 B (MODE3 epilogue floor)
    cudaFuncSetAttribute(k_conv<256,5,2,1>, cudaFuncAttributeMaxDynamicSharedMemorySize, smem5);
    cudaFuncSetAttribute(k_conv<512,5,2,2>, cudaFuncAttributeMaxDynamicSharedMemorySize, smem5);

    // FiLM scale/shift
    k_ss<<<64, 256>>>(t, tm_w, tm_b);
    // residual 1x1 conv -> d_out (must precede fused conv1)
    k_conv<256,1,0,0><<<dim3(4,8,64), 256, smem1>>>(x, res_w, res_b, out, 512, nullptr, nullptr);
    // conv0 + GN0 + FiLM + mish -> g_h2
    k_conv<256,5,2,1><<<dim3(4,8,64), 256, smem5>>>(x, conv0_w, conv0_b, p_h2, 512, gn0_g, gn0_b);
    // conv1 + GN1 + mish + residual add -> d_out
    k_conv<512,5,2,2><<<dim3(4,8,64), 256, smem5>>>(p_h2, conv1_w, conv1_b, out, 512, gn1_g, gn1_b);
    // LN over channels of out[cidx] -> g_xln (b,c,t)
    k_xln<<<dim3(4,64), 128>>>(out, ln_x_g, ln_x_b, cidx);
    // q projection + softmax over head-dim -> g_q
    k_conv<512,1,0,3><<<dim3(4,8,64), 256, smem3>>>(p_xln, q_w, q_b, p_q, 512, nullptr, nullptr);
    // LN(cond[cidx]) -> g_cn (b, 768, 77)
    k_cn<<<dim3(77,64), 256>>>(cond, ln_c_g, ln_c_b, cidx);
    // k,v projections (1x1 conv over 768 ch, L=77)
    k_conv<768,1,0,0><<<dim3(1,8,64), 256, smem1>>>(p_cn, k_w, k_b, p_k, 77, nullptr, nullptr);
    k_conv<768,1,0,0><<<dim3(1,8,64), 256, smem1>>>(p_cn, v_w, v_b, p_v, 77, nullptr, nullptr);
    // k softmax over n
    k_ksm<<<dim3(64,64), 256>>>(p_k);
    // attn = k^T v per (b,h)
    k_attn<<<dim3(8,64), 256>>>(p_k, p_v);
    // y = q @ attn, add into d_out
    k_y<<<dim3(4,8,64), 256>>>(p_q, out, cidx);
}

// round 7
// speedup vs baseline: 1.9018x; 1.1006x over previous
#include <cuda_runtime.h>
#include <math.h>
#include <stdint.h>

#define EPSV 1e-5f

// ---------------- scratch (allocation-free: device globals) ----------------
__device__ float    g_ss  [64*1024];
__device__ uint32_t g_xt  [64*256*512];   // tf32(x)
__device__ uint32_t g_h2  [64*512*512];   // tf32(conv0 block output)
__device__ uint32_t g_xln [64*512*512];   // tf32(LN(out))
__device__ float    g_q   [64*512*512];
__device__ uint32_t g_cn  [64*768*77];    // tf32(LN(cond)) transposed
__device__ float    g_k   [64*512*77];
__device__ float    g_v   [64*512*77];
__device__ float    g_attn[64*8*64*64];
// tf32 weight copies
__device__ uint32_t g_w0[512*256*5];
__device__ uint32_t g_w1[512*512*5];
__device__ uint32_t g_wr[512*256];
__device__ uint32_t g_wq[512*512];
__device__ uint32_t g_wk[512*768];
__device__ uint32_t g_wv[512*768];

// fast mish: x * tanh(softplus(x)) ; tanh(log u) = (u^2-1)/(u^2+1), u = 1+e^x
__device__ __forceinline__ float mishf(float x){
    float xc = fminf(x, 15.f);
    float e  = __expf(xc);
    float u  = 1.f + e;
    float u2 = u * u;
    return x * __fdividef(u2 - 1.f, u2 + 1.f);
}

// ---------------- tf32 mma helpers ------------------------------------------
__device__ __forceinline__ uint32_t f2tf32(float f){
    uint32_t r; asm("cvt.rna.tf32.f32 %0, %1;" : "=r"(r) : "f"(f)); return r;
}
__device__ __forceinline__ void mma_tf32(float* c, uint32_t a0, uint32_t a1,
                                         uint32_t a2, uint32_t a3,
                                         uint32_t b0, uint32_t b1){
    asm("mma.sync.aligned.m16n8k8.row.col.f32.tf32.tf32.f32 "
        "{%0,%1,%2,%3}, {%4,%5,%6,%7}, {%8,%9}, {%0,%1,%2,%3};"
        : "+f"(c[0]), "+f"(c[1]), "+f"(c[2]), "+f"(c[3])
        : "r"(a0), "r"(a1), "r"(a2), "r"(a3), "r"(b0), "r"(b1));
}

// ---------------- cp.async helpers -------------------------------------------
__device__ __forceinline__ void cp4(uint32_t dst, const void* src, bool pred){
    int sz = pred ? 4 : 0;
    asm volatile("cp.async.ca.shared.global [%0], [%1], 4, %2;"
                 :: "r"(dst), "l"(src), "r"(sz));
}
__device__ __forceinline__ void cp16(uint32_t dst, const void* src){
    asm volatile("cp.async.cg.shared.global [%0], [%1], 16;" :: "r"(dst), "l"(src));
}
__device__ __forceinline__ void cp_commit(){
    asm volatile("cp.async.commit_group;");
}
template<int N>
__device__ __forceinline__ void cp_wait(){
    asm volatile("cp.async.wait_group %0;" :: "n"(N));
}

// ---------------- elementwise float -> tf32 bits -----------------------------
__global__ void k_cvt(const float* __restrict__ src, uint32_t* __restrict__ dst, int n){
    int i = blockIdx.x*256 + threadIdx.x;
    int stride = gridDim.x*256;
    for (; i < n; i += stride) dst[i] = f2tf32(src[i]);
}

// ---------------- ss = mish(t) @ tm_w^T + tm_b -----------------------------
__global__ void k_ss(const float* __restrict__ t, const float* __restrict__ w,
                     const float* __restrict__ bias){
    __shared__ float tm[512];
    int b = blockIdx.x, tid = threadIdx.x;
    for (int i = tid; i < 512; i += 256) tm[i] = mishf(t[b*512 + i]);
    __syncthreads();
    for (int o = tid; o < 1024; o += 256){
        const float* wr = w + (size_t)o * 512;
        float acc = bias[o];
        #pragma unroll 8
        for (int i = 0; i < 512; i++) acc = fmaf(tm[i], wr[i], acc);
        g_ss[b*1024 + o] = acc;
    }
}

// ---------------- conv1d as implicit GEMM on tf32 tensor cores --------------
// Inputs/weights are pre-converted tf32 bit patterns: mainloop is LDS+MMA only.
// MODE 0: plain bias (res conv, k/v proj)
// MODE 1: + GN + FiLM + mish, output tf32 bits   (conv0 -> conv1 input)
// MODE 2: + GN + mish + res add (fp32 out)       (conv1)
// MODE 3: + softmax over 64 rows (fp32 out)      (q proj)
// Block: 256 thr = 8 warps (2m x 4n). Block tile M=64(co) x N=128(l).
template<int CIN, int TAPS, int PAD, int MODE>
__global__ void k_conv(const uint32_t* __restrict__ in, const uint32_t* __restrict__ w,
                       const float* __restrict__ bias, float* __restrict__ out, int L,
                       const float* __restrict__ gg, const float* __restrict__ gb){
    constexpr int LWD = 128 + TAPS - 1;   // valid data columns in xs
    constexpr int LWS = 136;              // padded xs row stride
    constexpr int KCH = 16*TAPS;          // weights per co per chunk
    constexpr int WST = KCH + 4;          // ws row stride
    constexpr int CHUNK = 16*LWS + 64*WST;
    constexpr int EST = 132;              // epilogue tile row stride
    extern __shared__ __align__(16) uint32_t smu[];
    __shared__ float red0[256], red1[256];
    __shared__ float stA[128], stB[128];
    __shared__ float rg[64], rb[64], rsc[64], rsh[64];

    const int l0 = blockIdx.x*128, co0 = blockIdx.y*64, b = blockIdx.z;
    const int COUT = gridDim.y*64;
    const int tid = threadIdx.x, lane = tid & 31, wid = tid >> 5;
    const int wm = (wid & 1)*32, wn = (wid >> 1)*32;
    const int qr = lane >> 2, qc = lane & 3;
    const uint32_t smaddr = (uint32_t)__cvta_generic_to_shared(smu);

    float acc[2][4][4];
    #pragma unroll
    for (int mi = 0; mi < 2; mi++)
        #pragma unroll
        for (int ni = 0; ni < 4; ni++)
            #pragma unroll
            for (int r = 0; r < 4; r++) acc[mi][ni][r] = 0.f;

    const uint32_t* inb = in + (size_t)b*CIN*L;

    auto fill = [&](int ci0, int stg){
        uint32_t xsA = smaddr + stg*CHUNK*4;
        uint32_t wsA = xsA + 16*LWS*4;
        for (int idx = tid; idx < 16*LWD; idx += 256){
            int r = idx / LWD, c = idx - r*LWD;
            int l = l0 + c - PAD;
            bool ok = (l >= 0 && l < L);
            int lc = ok ? l : 0;
            cp4(xsA + (r*LWS + c)*4, inb + (size_t)(ci0 + r)*L + lc, ok);
        }
        for (int idx = tid; idx < 64*(KCH/4); idx += 256){
            int c = idx / (KCH/4), j = idx - c*(KCH/4);
            cp16(wsA + (c*WST + 4*j)*4,
                 w + ((size_t)(co0 + c)*CIN + ci0)*TAPS + 4*j);
        }
    };

    const int NCH = CIN/16;
    fill(0, 0);
    cp_commit();

    for (int ch = 0; ch < NCH; ch++){
        if (ch + 1 < NCH) fill((ch + 1)*16, (ch + 1) & 1);
        cp_commit();
        cp_wait<1>();
        __syncthreads();

        const uint32_t (*xs)[LWS] = (const uint32_t(*)[LWS])(smu + (ch & 1)*CHUNK);
        const uint32_t (*ws)[WST] = (const uint32_t(*)[WST])(smu + (ch & 1)*CHUNK + 16*LWS);

        #pragma unroll
        for (int tap = 0; tap < TAPS; tap++){
            #pragma unroll
            for (int ks = 0; ks < 2; ks++){
                uint32_t A[2][4], B[4][2];
                const int k0 = ks*8 + qc;
                #pragma unroll
                for (int mi = 0; mi < 2; mi++){
                    int m = wm + mi*16 + qr;
                    A[mi][0] = ws[m    ][ k0     *TAPS + tap];
                    A[mi][1] = ws[m + 8][ k0     *TAPS + tap];
                    A[mi][2] = ws[m    ][(k0 + 4)*TAPS + tap];
                    A[mi][3] = ws[m + 8][(k0 + 4)*TAPS + tap];
                }
                #pragma unroll
                for (int ni = 0; ni < 4; ni++){
                    int n = wn + ni*8 + qr + tap;
                    B[ni][0] = xs[k0    ][n];
                    B[ni][1] = xs[k0 + 4][n];
                }
                #pragma unroll
                for (int mi = 0; mi < 2; mi++)
                    #pragma unroll
                    for (int ni = 0; ni < 4; ni++){
                        mma_tf32(acc[mi][ni], A[mi][0], A[mi][1], A[mi][2], A[mi][3],
                                 B[ni][0], B[ni][1]);
                    }
            }
        }
        __syncthreads();
    }

    if (MODE == 0){
        #pragma unroll
        for (int mi = 0; mi < 2; mi++){
            int r0 = co0 + wm + mi*16 + qr;
            float b0 = bias[r0], b1 = bias[r0 + 8];
            #pragma unroll
            for (int ni = 0; ni < 4; ni++){
                int c0 = l0 + wn + ni*8 + 2*qc;
                float* C = acc[mi][ni];
                if (((L & 1) == 0) && (c0 + 1) < L){
                    *(float2*)&out[((size_t)b*COUT + r0    )*L + c0] = make_float2(C[0]+b0, C[1]+b0);
                    *(float2*)&out[((size_t)b*COUT + r0 + 8)*L + c0] = make_float2(C[2]+b1, C[3]+b1);
                } else {
                    if (c0 < L){
                        out[((size_t)b*COUT + r0    )*L + c0] = C[0] + b0;
                        out[((size_t)b*COUT + r0 + 8)*L + c0] = C[2] + b1;
                    }
                    if (c0 + 1 < L){
                        out[((size_t)b*COUT + r0    )*L + c0 + 1] = C[1] + b0;
                        out[((size_t)b*COUT + r0 + 8)*L + c0 + 1] = C[3] + b1;
                    }
                }
            }
        }
        return;
    }

    // ---- fused epilogue (full 64x128 tile; L == 512 here) ----
    float* et = (float*)smu;
    #pragma unroll
    for (int mi = 0; mi < 2; mi++){
        int r0 = wm + mi*16 + qr;
        float b0 = bias[co0 + r0], b1 = bias[co0 + r0 + 8];
        #pragma unroll
        for (int ni = 0; ni < 4; ni++){
            int c0 = wn + ni*8 + 2*qc;
            float* C = acc[mi][ni];
            *(float2*)&et[ r0     *EST + c0] = make_float2(C[0]+b0, C[1]+b0);
            *(float2*)&et[(r0 + 8)*EST + c0] = make_float2(C[2]+b1, C[3]+b1);
        }
    }
    if (MODE == 1 && tid < 64){
        rg[tid]  = gg[co0 + tid];            rb[tid]  = gb[co0 + tid];
        rsc[tid] = g_ss[b*1024 + co0 + tid]; rsh[tid] = g_ss[b*1024 + 512 + co0 + tid];
    }
    if (MODE == 2 && tid < 64){
        rg[tid] = gg[co0 + tid]; rb[tid] = gb[co0 + tid];
    }
    __syncthreads();

    const int c = tid & 127, half = tid >> 7;
    if (MODE == 1 || MODE == 2){
        float s = 0.f, q = 0.f;
        #pragma unroll
        for (int r = 0; r < 32; r++){
            float v = et[(half*32 + r)*EST + c];
            s += v; q += v*v;
        }
        red0[tid] = s; red1[tid] = q;
        __syncthreads();
        if (tid < 128){
            float S = red0[tid] + red0[tid + 128];
            float Q = red1[tid] + red1[tid + 128];
            float m = S * (1.f/64.f);
            stA[tid] = m;
            stB[tid] = rsqrtf(Q * (1.f/64.f) - m*m + EPSV);
        }
        __syncthreads();
    } else { // MODE == 3: softmax over 64 rows per column
        float m = -1e30f;
        #pragma unroll
        for (int r = 0; r < 32; r++) m = fmaxf(m, et[(half*32 + r)*EST + c]);
        red0[tid] = m;
        __syncthreads();
        if (tid < 128) stA[tid] = fmaxf(red0[tid], red0[tid + 128]);
        __syncthreads();
        float s = 0.f;
        #pragma unroll
        for (int r = 0; r < 32; r++) s += __expf(et[(half*32 + r)*EST + c] - stA[c]);
        red1[tid] = s;
        __syncthreads();
        if (tid < 128) stB[tid] = 1.f / (red1[tid] + red1[tid + 128]);
        __syncthreads();
    }

    #pragma unroll 4
    for (int k = 0; k < 32; k++){
        int idx = k*256 + tid;
        int r = idx >> 7, cc = idx & 127;
        float v = et[r*EST + cc];
        size_t gidx = ((size_t)b*COUT + co0 + r)*L + l0 + cc;
        if (MODE == 1){
            v = (v - stA[cc]) * stB[cc] * rg[r] + rb[r];
            v = v * (1.f + rsc[r]) + rsh[r];
            ((uint32_t*)out)[gidx] = f2tf32(mishf(v));
        } else if (MODE == 2){
            v = (v - stA[cc]) * stB[cc] * rg[r] + rb[r];
            out[gidx] = mishf(v) + out[gidx];
        } else { // MODE == 3
            out[gidx] = __expf(v - stA[cc]) * stB[cc];
        }
    }
}

// ---------------- LN over channels of out[cidx[b]] -> g_xln (tf32 bits) -----
__global__ void k_xln(const float* __restrict__ out, const float* __restrict__ gg,
                      const float* __restrict__ gb, const int* __restrict__ cidx){
    int b = blockIdx.y;
    int t = blockIdx.x*128 + threadIdx.x;
    int bi = cidx[b];
    const float* src = out + (size_t)bi*512*512 + t;
    float s = 0.f, q = 0.f;
    for (int c = 0; c < 512; c++){ float v = src[(size_t)c*512]; s += v; q += v*v; }
    float m = s * (1.f/512.f);
    float r = rsqrtf(q * (1.f/512.f) - m*m + EPSV);
    uint32_t* dst = g_xln + (size_t)b*512*512 + t;
    for (int c = 0; c < 512; c++){
        float v = src[(size_t)c*512];
        dst[(size_t)c*512] = f2tf32((v - m) * r * gg[c] + gb[c]);
    }
}

// ---------------- LN(cond[cidx[b]]) -> g_cn (tf32 bits, transposed) ---------
__global__ void k_cn(const float* __restrict__ cond, const float* __restrict__ gg,
                     const float* __restrict__ gb, const int* __restrict__ cidx){
    __shared__ float row[768];
    __shared__ float wsum[8], wsq[8];
    int n = blockIdx.x, b = blockIdx.y;
    int bi = cidx[b];
    int tid = threadIdx.x, lane = tid & 31, w = tid >> 5;
    const float* src = cond + ((size_t)bi*77 + n)*768;
    float s = 0.f, q = 0.f;
    for (int i = tid; i < 768; i += 256){ float v = src[i]; row[i] = v; s += v; q += v*v; }
    #pragma unroll
    for (int o = 16; o; o >>= 1){ s += __shfl_xor_sync(0xffffffffu, s, o); q += __shfl_xor_sync(0xffffffffu, q, o); }
    if (lane == 0){ wsum[w] = s; wsq[w] = q; }
    __syncthreads();
    if (tid == 0){
        float S = 0.f, Q = 0.f;
        #pragma unroll
        for (int i = 0; i < 8; i++){ S += wsum[i]; Q += wsq[i]; }
        float m = S * (1.f/768.f); float var = Q * (1.f/768.f) - m*m;
        wsum[0] = m; wsq[0] = rsqrtf(var + EPSV);
    }
    __syncthreads();
    float m = wsum[0], r = wsq[0];
    for (int i = tid; i < 768; i += 256)
        g_cn[((size_t)b*768 + i)*77 + n] = f2tf32((row[i] - m) * r * gg[i] + gb[i]);
}

// ---------------- k softmax over n (77) at fixed (b,d) ----------------------
__global__ void k_ksm(float* __restrict__ kbuf){
    int b = blockIdx.x;
    int d = blockIdx.y*8 + (threadIdx.x >> 5);
    int lane = threadIdx.x & 31;
    float* row = kbuf + ((size_t)b*512 + d)*77;
    float v0 = row[lane];
    float v1 = row[lane + 32];
    bool has2 = (lane + 64) < 77;
    float v2 = has2 ? row[lane + 64] : -1e30f;
    float m = fmaxf(fmaxf(v0, v1), v2);
    #pragma unroll
    for (int o = 16; o; o >>= 1) m = fmaxf(m, __shfl_xor_sync(0xffffffffu, m, o));
    float e0 = __expf(v0 - m), e1 = __expf(v1 - m), e2 = has2 ? __expf(v2 - m) : 0.f;
    float s = e0 + e1 + e2;
    #pragma unroll
    for (int o = 16; o; o >>= 1) s += __shfl_xor_sync(0xffffffffu, s, o);
    float inv = 1.f / s;
    row[lane] = e0 * inv;
    row[lane + 32] = e1 * inv;
    if (has2) row[lane + 64] = e2 * inv;
}

// ---------------- attn[b,h,d,l] = sum_n k[b,hd+d,n] * v[b,hd+l,n] ------------
__global__ void k_attn(const float* __restrict__ kbuf, const float* __restrict__ vbuf){
    __shared__ float ks[64][80], vs[64][80];
    int h = blockIdx.x, b = blockIdx.y;
    int tid = threadIdx.x, tx = tid & 15, ty = tid >> 4;
    const float* kp = kbuf + ((size_t)(b*512 + h*64))*77;
    const float* vp = vbuf + ((size_t)(b*512 + h*64))*77;
    for (int idx = tid; idx < 64*80; idx += 256){
        int r = idx / 80, c = idx - r*80;
        float kv = (c < 77) ? kp[(size_t)r*77 + c] : 0.f;
        float vv = (c < 77) ? vp[(size_t)r*77 + c] : 0.f;
        ks[r][c] = kv; vs[r][c] = vv;
    }
    __syncthreads();
    float acc[4][4];
    #pragma unroll
    for (int i = 0; i < 4; i++)
        #pragma unroll
        for (int j = 0; j < 4; j++) acc[i][j] = 0.f;
    for (int n = 0; n < 77; n++){
        float a[4], c4[4];
        #pragma unroll
        for (int i = 0; i < 4; i++) a[i] = ks[ty*4 + i][n];
        #pragma unroll
        for (int j = 0; j < 4; j++) c4[j] = vs[tx*4 + j][n];
        #pragma unroll
        for (int i = 0; i < 4; i++)
            #pragma unroll
            for (int j = 0; j < 4; j++) acc[i][j] = fmaf(a[i], c4[j], acc[i][j]);
    }
    #pragma unroll
    for (int i = 0; i < 4; i++)
        #pragma unroll
        for (int j = 0; j < 4; j++)
            g_attn[(((size_t)(b*8 + h))*64 + ty*4 + i)*64 + tx*4 + j] = acc[i][j];
}

// ---------------- y = q @ attn, add into d_out (cidx unique by construction) -
__global__ void k_y(const float* __restrict__ q, float* __restrict__ out,
                    const int* __restrict__ cidx){
    __shared__ __align__(16) float qs[64][128];
    __shared__ float as[64][64];
    int t0 = blockIdx.x*128, h = blockIdx.y, b = blockIdx.z;
    int bi = cidx[b];
    int tid = threadIdx.x, tx = tid & 15, ty = tid >> 4;
    for (int idx = tid; idx < 64*128; idx += 256){
        int r = idx >> 7, c = idx & 127;
        qs[r][c] = q[((size_t)(b*512 + h*64 + r))*512 + t0 + c];
    }
    for (int idx = tid; idx < 64*64; idx += 256){
        int r = idx >> 6, c = idx & 63;
        as[r][c] = g_attn[(((size_t)(b*8 + h))*64 + r)*64 + c];
    }
    __syncthreads();
    float acc[4][8];
    #pragma unroll
    for (int i = 0; i < 4; i++)
        #pragma unroll
        for (int j = 0; j < 8; j++) acc[i][j] = 0.f;
    for (int d = 0; d < 64; d++){
        float4 q0 = *reinterpret_cast<const float4*>(&qs[d][tx*8]);
        float4 q1 = *reinterpret_cast<const float4*>(&qs[d][tx*8 + 4]);
        float qr[8] = {q0.x,q0.y,q0.z,q0.w,q1.x,q1.y,q1.z,q1.w};
        float ar[4];
        #pragma unroll
        for (int i = 0; i < 4; i++) ar[i] = as[d][ty*4 + i];
        #pragma unroll
        for (int i = 0; i < 4; i++)
            #pragma unroll
            for (int j = 0; j < 8; j++) acc[i][j] = fmaf(ar[i], qr[j], acc[i][j]);
    }
    #pragma unroll
    for (int i = 0; i < 4; i++){
        int ch = h*64 + ty*4 + i;
        float* dst = &out[((size_t)bi*512 + ch)*512 + t0 + tx*8];
        float4 o0 = *(float4*)dst;
        float4 o1 = *(float4*)(dst + 4);
        o0.x += acc[i][0]; o0.y += acc[i][1]; o0.z += acc[i][2]; o0.w += acc[i][3];
        o1.x += acc[i][4]; o1.y += acc[i][5]; o1.z += acc[i][6]; o1.w += acc[i][7];
        *(float4*)dst = o0;
        *(float4*)(dst + 4) = o1;
    }
}

// ---------------- launch ----------------------------------------------------
extern "C" void kernel_launch(void* const* d_in, const int* in_sizes, int n_in,
                              void* d_out, int out_size){
    const float* x       = (const float*)d_in[0];
    const float* t       = (const float*)d_in[1];
    const float* cond    = (const float*)d_in[2];
    const float* conv0_w = (const float*)d_in[3];
    const float* conv0_b = (const float*)d_in[4];
    const float* gn0_g   = (const float*)d_in[5];
    const float* gn0_b   = (const float*)d_in[6];
    const float* tm_w    = (const float*)d_in[7];
    const float* tm_b    = (const float*)d_in[8];
    const float* conv1_w = (const float*)d_in[9];
    const float* conv1_b = (const float*)d_in[10];
    const float* gn1_g   = (const float*)d_in[11];
    const float* gn1_b   = (const float*)d_in[12];
    const float* res_w   = (const float*)d_in[13];
    const float* res_b   = (const float*)d_in[14];
    const float* ln_x_g  = (const float*)d_in[15];
    const float* ln_x_b  = (const float*)d_in[16];
    const float* ln_c_g  = (const float*)d_in[17];
    const float* ln_c_b  = (const float*)d_in[18];
    const float* q_w     = (const float*)d_in[19];
    const float* q_b     = (const float*)d_in[20];
    const float* k_w     = (const float*)d_in[21];
    const float* k_b     = (const float*)d_in[22];
    const float* v_w     = (const float*)d_in[23];
    const float* v_b     = (const float*)d_in[24];
    const int*   cidx    = (const int*)d_in[25];
    float* out = (float*)d_out;

    uint32_t *p_xt, *p_h2, *p_xln, *p_cn;
    uint32_t *p_w0, *p_w1, *p_wr, *p_wq, *p_wk, *p_wv;
    float *p_q, *p_k, *p_v;
    cudaGetSymbolAddress((void**)&p_xt,  g_xt);
    cudaGetSymbolAddress((void**)&p_h2,  g_h2);
    cudaGetSymbolAddress((void**)&p_xln, g_xln);
    cudaGetSymbolAddress((void**)&p_q,   g_q);
    cudaGetSymbolAddress((void**)&p_cn,  g_cn);
    cudaGetSymbolAddress((void**)&p_k,   g_k);
    cudaGetSymbolAddress((void**)&p_v,   g_v);
    cudaGetSymbolAddress((void**)&p_w0,  g_w0);
    cudaGetSymbolAddress((void**)&p_w1,  g_w1);
    cudaGetSymbolAddress((void**)&p_wr,  g_wr);
    cudaGetSymbolAddress((void**)&p_wq,  g_wq);
    cudaGetSymbolAddress((void**)&p_wk,  g_wk);
    cudaGetSymbolAddress((void**)&p_wv,  g_wv);

    const int smem5 = 2*(16*136 + 64*84)*4;   // 60416 B (5-tap)
    const int smem1 = 2*(16*136 + 64*20)*4;   // 27648 B (1-tap MODE0)
    const int smem3 = 8448*4;                 // 33792 B (MODE3 epilogue floor)
    cudaFuncSetAttribute(k_conv<256,5,2,1>, cudaFuncAttributeMaxDynamicSharedMemorySize, smem5);
    cudaFuncSetAttribute(k_conv<512,5,2,2>, cudaFuncAttributeMaxDynamicSharedMemorySize, smem5);

    // pre-convert inputs/weights to tf32 bits
    k_cvt<<<512, 256>>>(x, p_xt, 64*256*512);
    k_cvt<<<160, 256>>>(conv0_w, p_w0, 512*256*5);
    k_cvt<<<320, 256>>>(conv1_w, p_w1, 512*512*5);
    k_cvt<<<64,  256>>>(res_w,   p_wr, 512*256);
    k_cvt<<<64,  256>>>(q_w,     p_wq, 512*512);
    k_cvt<<<96,  256>>>(k_w,     p_wk, 512*768);
    k_cvt<<<96,  256>>>(v_w,     p_wv, 512*768);

    // FiLM scale/shift
    k_ss<<<64, 256>>>(t, tm_w, tm_b);
    // residual 1x1 conv -> d_out (must precede fused conv1)
    k_conv<256,1,0,0><<<dim3(4,8,64), 256, smem1>>>(p_xt, p_wr, res_b, out, 512, nullptr, nullptr);
    // conv0 + GN0 + FiLM + mish -> g_h2 (tf32)
    k_conv<256,5,2,1><<<dim3(4,8,64), 256, smem5>>>(p_xt, p_w0, conv0_b, (float*)p_h2, 512, gn0_g, gn0_b);
    // conv1 + GN1 + mish + residual add -> d_out
    k_conv<512,5,2,2><<<dim3(4,8,64), 256, smem5>>>(p_h2, p_w1, conv1_b, out, 512, gn1_g, gn1_b);
    // LN over channels of out[cidx] -> g_xln (tf32)
    k_xln<<<dim3(4,64), 128>>>(out, ln_x_g, ln_x_b, cidx);
    // q projection + softmax over head-dim -> g_q
    k_conv<512,1,0,3><<<dim3(4,8,64), 256, smem3>>>(p_xln, p_wq, q_b, p_q, 512, nullptr, nullptr);
    // LN(cond[cidx]) -> g_cn (tf32, transposed)
    k_cn<<<dim3(77,64), 256>>>(cond, ln_c_g, ln_c_b, cidx);
    // k,v projections (1x1 conv over 768 ch, L=77)
    k_conv<768,1,0,0><<<dim3(1,8,64), 256, smem1>>>(p_cn, p_wk, k_b, p_k, 77, nullptr, nullptr);
    k_conv<768,1,0,0><<<dim3(1,8,64), 256, smem1>>>(p_cn, p_wv, v_b, p_v, 77, nullptr, nullptr);
    // k softmax over n
    k_ksm<<<dim3(64,64), 256>>>(p_k);
    // attn = k^T v per (b,h)
    k_attn<<<dim3(8,64), 256>>>(p_k, p_v);
    // y = q @ attn, add into d_out
    k_y<<<dim3(4,8,64), 256>>>(p_q, out, cidx);
}

// round 8
// speedup vs baseline: 1.9351x; 1.0175x over previous
#include <cuda_runtime.h>
#include <math.h>
#include <stdint.h>

#define EPSV 1e-5f

// ---------------- scratch (allocation-free: device globals) ----------------
__device__ float    g_ss  [64*1024];
__device__ uint32_t g_xt  [64*256*512];   // tf32(x)
__device__ uint32_t g_h2  [64*512*512];   // tf32(conv0 block output)
__device__ uint32_t g_xln [64*512*512];   // tf32(LN(out))
__device__ float    g_q   [64*512*512];
__device__ uint32_t g_cn  [64*768*77];    // tf32(LN(cond)) transposed
__device__ float    g_k   [64*512*77];
__device__ float    g_v   [64*512*77];
__device__ float    g_attn[64*8*64*64];
// fragment-permuted tf32 weight copies
__device__ uint32_t g_w0[512*256*5];
__device__ uint32_t g_w1[512*512*5];
__device__ uint32_t g_wr[512*256];
__device__ uint32_t g_wq[512*512];
__device__ uint32_t g_wk[512*768];
__device__ uint32_t g_wv[512*768];

// fast mish
__device__ __forceinline__ float mishf(float x){
    float xc = fminf(x, 15.f);
    float e  = __expf(xc);
    float u  = 1.f + e;
    float u2 = u * u;
    return x * __fdividef(u2 - 1.f, u2 + 1.f);
}

// ---------------- tf32 mma helpers ------------------------------------------
__device__ __forceinline__ uint32_t f2tf32(float f){
    uint32_t r; asm("cvt.rna.tf32.f32 %0, %1;" : "=r"(r) : "f"(f)); return r;
}
__device__ __forceinline__ void mma_tf32(float* c, uint32_t a0, uint32_t a1,
                                         uint32_t a2, uint32_t a3,
                                         uint32_t b0, uint32_t b1){
    asm("mma.sync.aligned.m16n8k8.row.col.f32.tf32.tf32.f32 "
        "{%0,%1,%2,%3}, {%4,%5,%6,%7}, {%8,%9}, {%0,%1,%2,%3};"
        : "+f"(c[0]), "+f"(c[1]), "+f"(c[2]), "+f"(c[3])
        : "r"(a0), "r"(a1), "r"(a2), "r"(a3), "r"(b0), "r"(b1));
}

// ---------------- cp.async helpers -------------------------------------------
__device__ __forceinline__ void cp4(uint32_t dst, const void* src, bool pred){
    int sz = pred ? 4 : 0;
    asm volatile("cp.async.ca.shared.global [%0], [%1], 4, %2;"
                 :: "r"(dst), "l"(src), "r"(sz));
}
__device__ __forceinline__ void cp16(uint32_t dst, const void* src){
    asm volatile("cp.async.cg.shared.global [%0], [%1], 16;" :: "r"(dst), "l"(src));
}
__device__ __forceinline__ void cp_commit(){
    asm volatile("cp.async.commit_group;");
}
template<int N>
__device__ __forceinline__ void cp_wait(){
    asm volatile("cp.async.wait_group %0;" :: "n"(N));
}

// ---------------- elementwise float -> tf32 bits -----------------------------
__global__ void k_cvt(const float* __restrict__ src, uint32_t* __restrict__ dst, int n){
    int i = blockIdx.x*256 + threadIdx.x;
    int stride = gridDim.x*256;
    for (; i < n; i += stride) dst[i] = f2tf32(src[i]);
}

// ---------------- weight prep: tf32 + fragment permutation -------------------
// dst flat layout: [coblk][cichunk][s(4)][step(2*TAPS)][lane(32)][j(4)]
// j quad = (qr,k0), (qr+8,k0), (qr,k0+4), (qr+8,k0+4); k0 = ks*8+qc (ci-local)
template<int CIN, int TAPS>
__global__ void k_wprep(const float* __restrict__ w, uint32_t* __restrict__ dst){
    const int NCH = CIN/16;
    int n = 512*CIN*TAPS;
    int f = blockIdx.x*256 + threadIdx.x;
    int stride = gridDim.x*256;
    for (; f < n; f += stride){
        int j    = f & 3;
        int rem  = f >> 2;
        int lane = rem & 31;  rem >>= 5;
        int step = rem % (2*TAPS); rem /= (2*TAPS);
        int s    = rem & 3;   rem >>= 2;
        int ch   = rem % NCH;
        int cb   = rem / NCH;
        int qr = lane >> 2, qc = lane & 3;
        int tap = step >> 1, ks = step & 1;
        int co = cb*64 + s*16 + qr + (j & 1)*8;
        int ci = ch*16 + ks*8 + qc + (j >> 1)*4;
        dst[f] = f2tf32(w[((size_t)co*CIN + ci)*TAPS + tap]);
    }
}

// ---------------- ss = mish(t) @ tm_w^T + tm_b -----------------------------
__global__ void k_ss(const float* __restrict__ t, const float* __restrict__ w,
                     const float* __restrict__ bias){
    __shared__ float tm[512];
    int b = blockIdx.x, tid = threadIdx.x;
    for (int i = tid; i < 512; i += 256) tm[i] = mishf(t[b*512 + i]);
    __syncthreads();
    for (int o = tid; o < 1024; o += 256){
        const float* wr = w + (size_t)o * 512;
        float acc = bias[o];
        #pragma unroll 8
        for (int i = 0; i < 512; i++) acc = fmaf(tm[i], wr[i], acc);
        g_ss[b*1024 + o] = acc;
    }
}

// ---------------- conv1d as implicit GEMM on tf32 tensor cores --------------
// Warp tile m=64 x n=16 (8 warps in n). A loads are LDS.128 from permuted ws.
// MODE 0: plain bias (res conv, k/v proj)
// MODE 1: + GN + FiLM + mish, output tf32 bits   (conv0 -> conv1 input)
// MODE 2: + GN + mish + res add (fp32 out)       (conv1)
// MODE 3: + softmax over 64 rows (fp32 out)      (q proj)
template<int CIN, int TAPS, int PAD, int MODE>
__global__ void k_conv(const uint32_t* __restrict__ in, const uint32_t* __restrict__ w,
                       const float* __restrict__ bias, float* __restrict__ out, int L,
                       const float* __restrict__ gg, const float* __restrict__ gb){
    constexpr int LWD = 128 + TAPS - 1;
    constexpr int LWS = 136;
    constexpr int KC  = 16*TAPS;          // K per chunk
    constexpr int NCH_T = 0;              // silence unused warnings
    constexpr int CHUNK = 16*LWS + 64*KC; // u32 per stage
    constexpr int EST = 132;
    extern __shared__ __align__(16) uint32_t smu[];
    __shared__ float red0[256], red1[256];
    __shared__ float stA[128], stB[128];
    __shared__ float rg[64], rb[64], rsc[64], rsh[64];
    (void)NCH_T;

    const int l0 = blockIdx.x*128, co0 = blockIdx.y*64, b = blockIdx.z;
    const int COUT = gridDim.y*64;
    const int tid = threadIdx.x, lane = tid & 31, wid = tid >> 5;
    const int wn = wid*16;
    const int qr = lane >> 2, qc = lane & 3;
    const uint32_t smaddr = (uint32_t)__cvta_generic_to_shared(smu);
    const int NCH = CIN/16;

    float acc[4][2][4];
    #pragma unroll
    for (int s = 0; s < 4; s++)
        #pragma unroll
        for (int ni = 0; ni < 2; ni++)
            #pragma unroll
            for (int r = 0; r < 4; r++) acc[s][ni][r] = 0.f;

    const uint32_t* inb = in + (size_t)b*CIN*L;
    const uint32_t* wblk = w + ((size_t)blockIdx.y*NCH)*64*KC;

    auto fill = [&](int ch, int stg){
        uint32_t xsA = smaddr + stg*CHUNK*4;
        uint32_t wsA = xsA + 16*LWS*4;
        const int ci0 = ch*16;
        for (int idx = tid; idx < 16*LWD; idx += 256){
            int r = idx / LWD, c = idx - r*LWD;
            int l = l0 + c - PAD;
            bool ok = (l >= 0 && l < L);
            int lc = ok ? l : 0;
            cp4(xsA + (r*LWS + c)*4, inb + (size_t)(ci0 + r)*L + lc, ok);
        }
        const uint32_t* wchunk = wblk + (size_t)ch*64*KC;
        for (int idx = tid; idx < 16*KC; idx += 256)   // 64*KC/4 quads
            cp16(wsA + idx*16, wchunk + idx*4);
    };

    fill(0, 0);
    cp_commit();

    for (int ch = 0; ch < NCH; ch++){
        if (ch + 1 < NCH) fill(ch + 1, (ch + 1) & 1);
        cp_commit();
        cp_wait<1>();
        __syncthreads();

        const uint32_t* xs = smu + (ch & 1)*CHUNK;          // [16][LWS]
        const uint32_t* wp = xs + 16*LWS;                   // permuted quads

        #pragma unroll
        for (int tap = 0; tap < TAPS; tap++){
            #pragma unroll
            for (int ks = 0; ks < 2; ks++){
                const int step = tap*2 + ks;
                const int k0 = ks*8 + qc;
                uint4 A[4];
                #pragma unroll
                for (int s = 0; s < 4; s++)
                    A[s] = *(const uint4*)&wp[((s*2*TAPS + step)*32 + lane)*4];
                uint32_t B0[2], B1[2];
                #pragma unroll
                for (int ni = 0; ni < 2; ni++){
                    int n = wn + ni*8 + qr + tap;
                    B0[ni] = xs[ k0     *LWS + n];
                    B1[ni] = xs[(k0 + 4)*LWS + n];
                }
                #pragma unroll
                for (int s = 0; s < 4; s++)
                    #pragma unroll
                    for (int ni = 0; ni < 2; ni++)
                        mma_tf32(acc[s][ni], A[s].x, A[s].y, A[s].z, A[s].w,
                                 B0[ni], B1[ni]);
            }
        }
        __syncthreads();
    }

    if (MODE == 0){
        #pragma unroll
        for (int s = 0; s < 4; s++){
            int r0 = co0 + s*16 + qr;
            float b0 = bias[r0], b1 = bias[r0 + 8];
            #pragma unroll
            for (int ni = 0; ni < 2; ni++){
                int c0 = l0 + wn + ni*8 + 2*qc;
                float* C = acc[s][ni];
                if (((L & 1) == 0) && (c0 + 1) < L){
                    *(float2*)&out[((size_t)b*COUT + r0    )*L + c0] = make_float2(C[0]+b0, C[1]+b0);
                    *(float2*)&out[((size_t)b*COUT + r0 + 8)*L + c0] = make_float2(C[2]+b1, C[3]+b1);
                } else {
                    if (c0 < L){
                        out[((size_t)b*COUT + r0    )*L + c0] = C[0] + b0;
                        out[((size_t)b*COUT + r0 + 8)*L + c0] = C[2] + b1;
                    }
                    if (c0 + 1 < L){
                        out[((size_t)b*COUT + r0    )*L + c0 + 1] = C[1] + b0;
                        out[((size_t)b*COUT + r0 + 8)*L + c0 + 1] = C[3] + b1;
                    }
                }
            }
        }
        return;
    }

    // ---- fused epilogue (full 64x128 tile; L == 512 here) ----
    float* et = (float*)smu;
    #pragma unroll
    for (int s = 0; s < 4; s++){
        int r0 = s*16 + qr;
        float b0 = bias[co0 + r0], b1 = bias[co0 + r0 + 8];
        #pragma unroll
        for (int ni = 0; ni < 2; ni++){
            int c0 = wn + ni*8 + 2*qc;
            float* C = acc[s][ni];
            *(float2*)&et[ r0     *EST + c0] = make_float2(C[0]+b0, C[1]+b0);
            *(float2*)&et[(r0 + 8)*EST + c0] = make_float2(C[2]+b1, C[3]+b1);
        }
    }
    if (MODE == 1 && tid < 64){
        rg[tid]  = gg[co0 + tid];            rb[tid]  = gb[co0 + tid];
        rsc[tid] = g_ss[b*1024 + co0 + tid]; rsh[tid] = g_ss[b*1024 + 512 + co0 + tid];
    }
    if (MODE == 2 && tid < 64){
        rg[tid] = gg[co0 + tid]; rb[tid] = gb[co0 + tid];
    }
    __syncthreads();

    const int c = tid & 127, half = tid >> 7;
    if (MODE == 1 || MODE == 2){
        float s = 0.f, q = 0.f;
        #pragma unroll
        for (int r = 0; r < 32; r++){
            float v = et[(half*32 + r)*EST + c];
            s += v; q += v*v;
        }
        red0[tid] = s; red1[tid] = q;
        __syncthreads();
        if (tid < 128){
            float S = red0[tid] + red0[tid + 128];
            float Q = red1[tid] + red1[tid + 128];
            float m = S * (1.f/64.f);
            stA[tid] = m;
            stB[tid] = rsqrtf(Q * (1.f/64.f) - m*m + EPSV);
        }
        __syncthreads();
    } else {
        float m = -1e30f;
        #pragma unroll
        for (int r = 0; r < 32; r++) m = fmaxf(m, et[(half*32 + r)*EST + c]);
        red0[tid] = m;
        __syncthreads();
        if (tid < 128) stA[tid] = fmaxf(red0[tid], red0[tid + 128]);
        __syncthreads();
        float s = 0.f;
        #pragma unroll
        for (int r = 0; r < 32; r++) s += __expf(et[(half*32 + r)*EST + c] - stA[c]);
        red1[tid] = s;
        __syncthreads();
        if (tid < 128) stB[tid] = 1.f / (red1[tid] + red1[tid + 128]);
        __syncthreads();
    }

    #pragma unroll 4
    for (int k = 0; k < 32; k++){
        int idx = k*256 + tid;
        int r = idx >> 7, cc = idx & 127;
        float v = et[r*EST + cc];
        size_t gidx = ((size_t)b*COUT + co0 + r)*L + l0 + cc;
        if (MODE == 1){
            v = (v - stA[cc]) * stB[cc] * rg[r] + rb[r];
            v = v * (1.f + rsc[r]) + rsh[r];
            ((uint32_t*)out)[gidx] = f2tf32(mishf(v));
        } else if (MODE == 2){
            v = (v - stA[cc]) * stB[cc] * rg[r] + rb[r];
            out[gidx] = mishf(v) + out[gidx];
        } else {
            out[gidx] = __expf(v - stA[cc]) * stB[cc];
        }
    }
}

// ---------------- LN over channels of out[cidx[b]] -> g_xln (tf32 bits) -----
__global__ void k_xln(const float* __restrict__ out, const float* __restrict__ gg,
                      const float* __restrict__ gb, const int* __restrict__ cidx){
    int b = blockIdx.y;
    int t = blockIdx.x*128 + threadIdx.x;
    int bi = cidx[b];
    const float* src = out + (size_t)bi*512*512 + t;
    float s = 0.f, q = 0.f;
    for (int c = 0; c < 512; c++){ float v = src[(size_t)c*512]; s += v; q += v*v; }
    float m = s * (1.f/512.f);
    float r = rsqrtf(q * (1.f/512.f) - m*m + EPSV);
    uint32_t* dst = g_xln + (size_t)b*512*512 + t;
    for (int c = 0; c < 512; c++){
        float v = src[(size_t)c*512];
        dst[(size_t)c*512] = f2tf32((v - m) * r * gg[c] + gb[c]);
    }
}

// ---------------- LN(cond[cidx[b]]) -> g_cn (tf32 bits, transposed) ---------
__global__ void k_cn(const float* __restrict__ cond, const float* __restrict__ gg,
                     const float* __restrict__ gb, const int* __restrict__ cidx){
    __shared__ float row[768];
    __shared__ float wsum[8], wsq[8];
    int n = blockIdx.x, b = blockIdx.y;
    int bi = cidx[b];
    int tid = threadIdx.x, lane = tid & 31, w = tid >> 5;
    const float* src = cond + ((size_t)bi*77 + n)*768;
    float s = 0.f, q = 0.f;
    for (int i = tid; i < 768; i += 256){ float v = src[i]; row[i] = v; s += v; q += v*v; }
    #pragma unroll
    for (int o = 16; o; o >>= 1){ s += __shfl_xor_sync(0xffffffffu, s, o); q += __shfl_xor_sync(0xffffffffu, q, o); }
    if (lane == 0){ wsum[w] = s; wsq[w] = q; }
    __syncthreads();
    if (tid == 0){
        float S = 0.f, Q = 0.f;
        #pragma unroll
        for (int i = 0; i < 8; i++){ S += wsum[i]; Q += wsq[i]; }
        float m = S * (1.f/768.f); float var = Q * (1.f/768.f) - m*m;
        wsum[0] = m; wsq[0] = rsqrtf(var + EPSV);
    }
    __syncthreads();
    float m = wsum[0], r = wsq[0];
    for (int i = tid; i < 768; i += 256)
        g_cn[((size_t)b*768 + i)*77 + n] = f2tf32((row[i] - m) * r * gg[i] + gb[i]);
}

// ---------------- k softmax over n (77) at fixed (b,d) ----------------------
__global__ void k_ksm(float* __restrict__ kbuf){
    int b = blockIdx.x;
    int d = blockIdx.y*8 + (threadIdx.x >> 5);
    int lane = threadIdx.x & 31;
    float* row = kbuf + ((size_t)b*512 + d)*77;
    float v0 = row[lane];
    float v1 = row[lane + 32];
    bool has2 = (lane + 64) < 77;
    float v2 = has2 ? row[lane + 64] : -1e30f;
    float m = fmaxf(fmaxf(v0, v1), v2);
    #pragma unroll
    for (int o = 16; o; o >>= 1) m = fmaxf(m, __shfl_xor_sync(0xffffffffu, m, o));
    float e0 = __expf(v0 - m), e1 = __expf(v1 - m), e2 = has2 ? __expf(v2 - m) : 0.f;
    float s = e0 + e1 + e2;
    #pragma unroll
    for (int o = 16; o; o >>= 1) s += __shfl_xor_sync(0xffffffffu, s, o);
    float inv = 1.f / s;
    row[lane] = e0 * inv;
    row[lane + 32] = e1 * inv;
    if (has2) row[lane + 64] = e2 * inv;
}

// ---------------- attn[b,h,d,l] = sum_n k[b,hd+d,n] * v[b,hd+l,n] ------------
__global__ void k_attn(const float* __restrict__ kbuf, const float* __restrict__ vbuf){
    __shared__ float ks[64][80], vs[64][80];
    int h = blockIdx.x, b = blockIdx.y;
    int tid = threadIdx.x, tx = tid & 15, ty = tid >> 4;
    const float* kp = kbuf + ((size_t)(b*512 + h*64))*77;
    const float* vp = vbuf + ((size_t)(b*512 + h*64))*77;
    for (int idx = tid; idx < 64*80; idx += 256){
        int r = idx / 80, c = idx - r*80;
        float kv = (c < 77) ? kp[(size_t)r*77 + c] : 0.f;
        float vv = (c < 77) ? vp[(size_t)r*77 + c] : 0.f;
        ks[r][c] = kv; vs[r][c] = vv;
    }
    __syncthreads();
    float acc[4][4];
    #pragma unroll
    for (int i = 0; i < 4; i++)
        #pragma unroll
        for (int j = 0; j < 4; j++) acc[i][j] = 0.f;
    for (int n = 0; n < 77; n++){
        float a[4], c4[4];
        #pragma unroll
        for (int i = 0; i < 4; i++) a[i] = ks[ty*4 + i][n];
        #pragma unroll
        for (int j = 0; j < 4; j++) c4[j] = vs[tx*4 + j][n];
        #pragma unroll
        for (int i = 0; i < 4; i++)
            #pragma unroll
            for (int j = 0; j < 4; j++) acc[i][j] = fmaf(a[i], c4[j], acc[i][j]);
    }
    #pragma unroll
    for (int i = 0; i < 4; i++)
        #pragma unroll
        for (int j = 0; j < 4; j++)
            g_attn[(((size_t)(b*8 + h))*64 + ty*4 + i)*64 + tx*4 + j] = acc[i][j];
}

// ---------------- y = q @ attn, add into d_out (cidx unique) -----------------
__global__ void k_y(const float* __restrict__ q, float* __restrict__ out,
                    const int* __restrict__ cidx){
    __shared__ __align__(16) float qs[64][128];
    __shared__ float as[64][64];
    int t0 = blockIdx.x*128, h = blockIdx.y, b = blockIdx.z;
    int bi = cidx[b];
    int tid = threadIdx.x, tx = tid & 15, ty = tid >> 4;
    for (int idx = tid; idx < 64*128; idx += 256){
        int r = idx >> 7, c = idx & 127;
        qs[r][c] = q[((size_t)(b*512 + h*64 + r))*512 + t0 + c];
    }
    for (int idx = tid; idx < 64*64; idx += 256){
        int r = idx >> 6, c = idx & 63;
        as[r][c] = g_attn[(((size_t)(b*8 + h))*64 + r)*64 + c];
    }
    __syncthreads();
    float acc[4][8];
    #pragma unroll
    for (int i = 0; i < 4; i++)
        #pragma unroll
        for (int j = 0; j < 8; j++) acc[i][j] = 0.f;
    for (int d = 0; d < 64; d++){
        float4 q0 = *reinterpret_cast<const float4*>(&qs[d][tx*8]);
        float4 q1 = *reinterpret_cast<const float4*>(&qs[d][tx*8 + 4]);
        float qr[8] = {q0.x,q0.y,q0.z,q0.w,q1.x,q1.y,q1.z,q1.w};
        float ar[4];
        #pragma unroll
        for (int i = 0; i < 4; i++) ar[i] = as[d][ty*4 + i];
        #pragma unroll
        for (int i = 0; i < 4; i++)
            #pragma unroll
            for (int j = 0; j < 8; j++) acc[i][j] = fmaf(ar[i], qr[j], acc[i][j]);
    }
    #pragma unroll
    for (int i = 0; i < 4; i++){
        int ch = h*64 + ty*4 + i;
        float* dst = &out[((size_t)bi*512 + ch)*512 + t0 + tx*8];
        float4 o0 = *(float4*)dst;
        float4 o1 = *(float4*)(dst + 4);
        o0.x += acc[i][0]; o0.y += acc[i][1]; o0.z += acc[i][2]; o0.w += acc[i][3];
        o1.x += acc[i][4]; o1.y += acc[i][5]; o1.z += acc[i][6]; o1.w += acc[i][7];
        *(float4*)dst = o0;
        *(float4*)(dst + 4) = o1;
    }
}

// ---------------- launch ----------------------------------------------------
extern "C" void kernel_launch(void* const* d_in, const int* in_sizes, int n_in,
                              void* d_out, int out_size){
    const float* x       = (const float*)d_in[0];
    const float* t       = (const float*)d_in[1];
    const float* cond    = (const float*)d_in[2];
    const float* conv0_w = (const float*)d_in[3];
    const float* conv0_b = (const float*)d_in[4];
    const float* gn0_g   = (const float*)d_in[5];
    const float* gn0_b   = (const float*)d_in[6];
    const float* tm_w    = (const float*)d_in[7];
    const float* tm_b    = (const float*)d_in[8];
    const float* conv1_w = (const float*)d_in[9];
    const float* conv1_b = (const float*)d_in[10];
    const float* gn1_g   = (const float*)d_in[11];
    const float* gn1_b   = (const float*)d_in[12];
    const float* res_w   = (const float*)d_in[13];
    const float* res_b   = (const float*)d_in[14];
    const float* ln_x_g  = (const float*)d_in[15];
    const float* ln_x_b  = (const float*)d_in[16];
    const float* ln_c_g  = (const float*)d_in[17];
    const float* ln_c_b  = (const float*)d_in[18];
    const float* q_w     = (const float*)d_in[19];
    const float* q_b     = (const float*)d_in[20];
    const float* k_w     = (const float*)d_in[21];
    const float* k_b     = (const float*)d_in[22];
    const float* v_w     = (const float*)d_in[23];
    const float* v_b     = (const float*)d_in[24];
    const int*   cidx    = (const int*)d_in[25];
    float* out = (float*)d_out;

    uint32_t *p_xt, *p_h2, *p_xln, *p_cn;
    uint32_t *p_w0, *p_w1, *p_wr, *p_wq, *p_wk, *p_wv;
    float *p_q, *p_k, *p_v;
    cudaGetSymbolAddress((void**)&p_xt,  g_xt);
    cudaGetSymbolAddress((void**)&p_h2,  g_h2);
    cudaGetSymbolAddress((void**)&p_xln, g_xln);
    cudaGetSymbolAddress((void**)&p_q,   g_q);
    cudaGetSymbolAddress((void**)&p_cn,  g_cn);
    cudaGetSymbolAddress((void**)&p_k,   g_k);
    cudaGetSymbolAddress((void**)&p_v,   g_v);
    cudaGetSymbolAddress((void**)&p_w0,  g_w0);
    cudaGetSymbolAddress((void**)&p_w1,  g_w1);
    cudaGetSymbolAddress((void**)&p_wr,  g_wr);
    cudaGetSymbolAddress((void**)&p_wq,  g_wq);
    cudaGetSymbolAddress((void**)&p_wk,  g_wk);
    cudaGetSymbolAddress((void**)&p_wv,  g_wv);

    const int smem5 = 2*(16*136 + 64*80)*4;   // 58368 B (5-tap)
    const int smem1 = 2*(16*136 + 64*16)*4;   // 25600 B (1-tap)
    const int smem3 = 8448*4;                 // 33792 B (MODE3 epilogue floor)
    cudaFuncSetAttribute(k_conv<256,5,2,1>, cudaFuncAttributeMaxDynamicSharedMemorySize, smem5);
    cudaFuncSetAttribute(k_conv<512,5,2,2>, cudaFuncAttributeMaxDynamicSharedMemorySize, smem5);

    // pre-convert input to tf32; weights to permuted tf32
    k_cvt<<<512, 256>>>(x, p_xt, 64*256*512);
    k_wprep<256,5><<<160, 256>>>(conv0_w, p_w0);
    k_wprep<512,5><<<320, 256>>>(conv1_w, p_w1);
    k_wprep<256,1><<<64,  256>>>(res_w,   p_wr);
    k_wprep<512,1><<<64,  256>>>(q_w,     p_wq);
    k_wprep<768,1><<<96,  256>>>(k_w,     p_wk);
    k_wprep<768,1><<<96,  256>>>(v_w,     p_wv);

    // FiLM scale/shift
    k_ss<<<64, 256>>>(t, tm_w, tm_b);
    // residual 1x1 conv -> d_out (must precede fused conv1)
    k_conv<256,1,0,0><<<dim3(4,8,64), 256, smem1>>>(p_xt, p_wr, res_b, out, 512, nullptr, nullptr);
    // conv0 + GN0 + FiLM + mish -> g_h2 (tf32)
    k_conv<256,5,2,1><<<dim3(4,8,64), 256, smem5>>>(p_xt, p_w0, conv0_b, (float*)p_h2, 512, gn0_g, gn0_b);
    // conv1 + GN1 + mish + residual add -> d_out
    k_conv<512,5,2,2><<<dim3(4,8,64), 256, smem5>>>(p_h2, p_w1, conv1_b, out, 512, gn1_g, gn1_b);
    // LN over channels of out[cidx] -> g_xln (tf32)
    k_xln<<<dim3(4,64), 128>>>(out, ln_x_g, ln_x_b, cidx);
    // q projection + softmax over head-dim -> g_q
    k_conv<512,1,0,3><<<dim3(4,8,64), 256, smem3>>>(p_xln, p_wq, q_b, p_q, 512, nullptr, nullptr);
    // LN(cond[cidx]) -> g_cn (tf32, transposed)
    k_cn<<<dim3(77,64), 256>>>(cond, ln_c_g, ln_c_b, cidx);
    // k,v projections (1x1 conv over 768 ch, L=77)
    k_conv<768,1,0,0><<<dim3(1,8,64), 256, smem1>>>(p_cn, p_wk, k_b, p_k, 77, nullptr, nullptr);
    k_conv<768,1,0,0><<<dim3(1,8,64), 256, smem1>>>(p_cn, p_wv, v_b, p_v, 77, nullptr, nullptr);
    // k softmax over n
    k_ksm<<<dim3(64,64), 256>>>(p_k);
    // attn = k^T v per (b,h)
    k_attn<<<dim3(8,64), 256>>>(p_k, p_v);
    // y = q @ attn, add into d_out
    k_y<<<dim3(4,8,64), 256>>>(p_q, out, cidx);
}